// round 9
// baseline (speedup 1.0000x reference)
#include <cuda_runtime.h>
#include <cstdint>
#include <math.h>

#define B_ 2
#define T_ 2048
#define M_ 1024
#define H_ 8
#define D_ 128
#define BH_ (B_*H_)

// Scratch (allocation-free: device globals)
__device__ float    g_q[BH_ * T_ * D_];        // [B,H,T,D] f32 (pre-rope)
__device__ float    g_k[BH_ * T_ * D_];        // [B,H,T,D] f32 (pre-rope)
__device__ uint32_t g_qt[BH_ * T_ * D_];       // tf32 q (post-rope)
__device__ uint32_t g_kt[BH_ * T_ * D_];       // tf32 k (post-rope)
__device__ uint32_t g_vt[BH_ * T_ * D_];       // tf32 v
__device__ uint32_t g_ot[B_ * T_ * H_ * D_];   // [B,T,H*D] tf32 (attention out)
__device__ uint32_t g_xt[B_ * T_ * M_];        // tf32(x)
__device__ uint32_t g_wtf[4 * M_ * M_];        // tf32(wq,wk,wv,wo)
__device__ float2   g_csn[T_ * 32];            // rope cos/sin table

__device__ __forceinline__ uint32_t f2tf(float x) {
    uint32_t r;
    asm("cvt.rna.tf32.f32 %0, %1;" : "=r"(r) : "f"(x));
    return r;
}
__device__ __forceinline__ float ex2(float x) {
    float r;
    asm("ex2.approx.ftz.f32 %0, %1;" : "=f"(r) : "f"(x));
    return r;
}
__device__ __forceinline__ void mma_tf32(float c[4], const uint32_t a[4],
                                         const uint32_t b[2]) {
    asm volatile(
        "mma.sync.aligned.m16n8k8.row.col.f32.tf32.tf32.f32 "
        "{%0,%1,%2,%3}, {%4,%5,%6,%7}, {%8,%9}, {%0,%1,%2,%3};"
        : "+f"(c[0]), "+f"(c[1]), "+f"(c[2]), "+f"(c[3])
        : "r"(a[0]), "r"(a[1]), "r"(a[2]), "r"(a[3]), "r"(b[0]), "r"(b[1]));
}
__device__ __forceinline__ void cp16(uint32_t smem_dst, const void* gptr) {
    asm volatile("cp.async.cg.shared.global [%0], [%1], 16;"
                 :: "r"(smem_dst), "l"(gptr));
}
#define CP_COMMIT() asm volatile("cp.async.commit_group;" ::: "memory")
#define CP_WAIT(n)  asm volatile("cp.async.wait_group %0;" :: "n"(n) : "memory")

// ---------------------------------------------------------------------------
// tf32 pre-conversion + rope table
// ---------------------------------------------------------------------------
__global__ void conv_x(const float* __restrict__ x)
{
    int i = blockIdx.x * 256 + threadIdx.x;
    float4 v = ((const float4*)x)[i];
    ((uint4*)g_xt)[i] = make_uint4(f2tf(v.x), f2tf(v.y), f2tf(v.z), f2tf(v.w));
}
__global__ void conv_w(const float* __restrict__ wq, const float* __restrict__ wk,
                       const float* __restrict__ wv, const float* __restrict__ wo)
{
    const float* src = (blockIdx.y == 0) ? wq : (blockIdx.y == 1) ? wk
                     : (blockIdx.y == 2) ? wv : wo;
    uint4* dst = (uint4*)(g_wtf + (size_t)blockIdx.y * M_ * M_);
    int i = blockIdx.x * 256 + threadIdx.x;
    float4 v = ((const float4*)src)[i];
    dst[i] = make_uint4(f2tf(v.x), f2tf(v.y), f2tf(v.z), f2tf(v.w));
}
__global__ void csn_kernel()
{
    int i = blockIdx.x * 256 + threadIdx.x;     // 65536 total
    int t = i >> 5, d = i & 31;
    float freq = powf(10000.0f, -(float)d * (1.0f / 32.0f));
    float sn, cs;
    sincosf((float)t * freq, &sn, &cs);
    g_csn[i] = make_float2(cs, sn);
}

// ---------------------------------------------------------------------------
// tf32 mma.sync GEMM v3: CTA tile 128x256, 8 warps (2m x 4n), warp tile 64x64,
// K-chunk 32, 3-stage cp.async. 1.0 LDS per HMMA.
// MODE 0: A = g_xt, W = g_wtf[z]; z=0,1 -> f32 g_q/g_k; z=2 -> tf32 g_vt.
// MODE 1: A = g_ot, W = g_wtf[3], f32 row-major store to Cout.
// ---------------------------------------------------------------------------
#define AP 36
#define BP 264
#define AS_WORDS (128 * AP)                    // 4608
#define BS_WORDS (32 * BP)                     // 8448
#define STG_WORDS (AS_WORDS + BS_WORDS)        // 13056
#define GEMM_SMEM_BYTES (3 * STG_WORDS * 4)    // 156672

template <int MODE>
__global__ void __launch_bounds__(256, 1) gemm_cp(float* __restrict__ Cout)
{
    extern __shared__ uint32_t smw[];

    const uint32_t* Ap;
    const uint32_t* W;
    if (MODE == 0) {
        Ap = g_xt;
        W  = g_wtf + (size_t)blockIdx.z * M_ * M_;
    } else {
        Ap = g_ot;
        W  = g_wtf + (size_t)3 * M_ * M_;
    }

    const int tid  = threadIdx.x;
    const int lane = tid & 31;
    const int wid  = tid >> 5;
    const int wm   = wid & 1;        // 2 m-warps
    const int wn   = wid >> 1;       // 4 n-warps
    const int g    = lane >> 2;
    const int lq   = lane & 3;

    const int r0 = blockIdx.y * 128;
    const int c0 = blockIdx.x * 256;

    const uint32_t smbase = (uint32_t)__cvta_generic_to_shared(smw);

    auto issue = [&](int c) {
        const int s = c % 3;
        const uint32_t aB = smbase + s * STG_WORDS * 4;
        const uint32_t bB = aB + AS_WORDS * 4;
        const int kc = c * 32;
        // A: 128 rows x 32 k = 1024 f4
#pragma unroll
        for (int it = 0; it < 4; it++) {
            int idx = tid + it * 256;
            int r = idx >> 3, k4 = idx & 7;
            cp16(aB + (r * AP + 4 * k4) * 4,
                 Ap + (size_t)(r0 + r) * 1024 + kc + 4 * k4);
        }
        // B: 32 k x 256 n = 2048 f4
#pragma unroll
        for (int it = 0; it < 8; it++) {
            int idx = tid + it * 256;
            int k = idx >> 6, n4 = idx & 63;
            cp16(bB + (k * BP + 4 * n4) * 4,
                 W + (size_t)(kc + k) * 1024 + c0 + 4 * n4);
        }
        CP_COMMIT();
    };

    float acc[4][8][4];
#pragma unroll
    for (int i = 0; i < 4; i++)
#pragma unroll
        for (int j = 0; j < 8; j++)
#pragma unroll
            for (int e = 0; e < 4; e++) acc[i][j][e] = 0.0f;

    issue(0);
    issue(1);

    for (int c = 0; c < 32; c++) {
        if (c < 30) { CP_WAIT(1); } else { CP_WAIT(0); }
        __syncthreads();

        const uint32_t* As = smw + (c % 3) * STG_WORDS;
        const uint32_t* Bs = As + AS_WORDS;

#pragma unroll
        for (int ks = 0; ks < 4; ks++) {
            const int kk = ks * 8;
            uint32_t afr[4][4];
#pragma unroll
            for (int mf = 0; mf < 4; mf++) {
                const uint32_t* p = &As[(wm * 64 + mf * 16 + g) * AP + kk + lq];
                afr[mf][0] = p[0];
                afr[mf][1] = p[8 * AP];
                afr[mf][2] = p[4];
                afr[mf][3] = p[8 * AP + 4];
            }
            uint32_t bfr[8][2];
#pragma unroll
            for (int nf = 0; nf < 8; nf++) {
                const uint32_t* p = &Bs[(kk + lq) * BP + wn * 64 + nf * 8 + g];
                bfr[nf][0] = p[0];
                bfr[nf][1] = p[4 * BP];
            }
#pragma unroll
            for (int mf = 0; mf < 4; mf++)
#pragma unroll
                for (int nf = 0; nf < 8; nf++)
                    mma_tf32(acc[mf][nf], afr[mf], bfr[nf]);
        }

        if (c + 2 < 32) issue(c + 2);
    }

    // ---- epilogue ----
#pragma unroll
    for (int mf = 0; mf < 4; mf++) {
#pragma unroll
        for (int half = 0; half < 2; half++) {
            int row = r0 + wm * 64 + mf * 16 + g + half * 8;
#pragma unroll
            for (int nf = 0; nf < 8; nf++) {
                int col = c0 + wn * 64 + nf * 8 + 2 * lq;
                float v0 = half ? acc[mf][nf][2] : acc[mf][nf][0];
                float v1 = half ? acc[mf][nf][3] : acc[mf][nf][1];
                if (MODE == 0) {
                    int bb = row >> 11, t = row & 2047;
                    int h = col >> 7, d = col & 127;
                    size_t off = ((size_t)(bb * H_ + h) * T_ + t) * D_ + d;
                    if (blockIdx.z == 2) {
                        *(uint2*)(g_vt + off) = make_uint2(f2tf(v0), f2tf(v1));
                    } else {
                        float* O = (blockIdx.z == 0) ? g_q : g_k;
                        *(float2*)(O + off) = make_float2(v0, v1);
                    }
                } else {
                    *(float2*)(Cout + (size_t)row * 1024 + col) =
                        make_float2(v0, v1);
                }
            }
        }
    }
}

// ---------------------------------------------------------------------------
// Fractional RoPE via precomputed table (memory-bound).
// ---------------------------------------------------------------------------
__global__ void rope_kernel()
{
    const int t  = blockIdx.x * 4 + (threadIdx.x >> 6);
    const int bh = blockIdx.y;
    const int r  = threadIdx.x & 63;
    const int d  = r & 31;
    const bool isq = (r < 32);
    const size_t off = ((size_t)bh * T_ + t) * D_;
    const float* src = (isq ? g_q : g_k) + off;
    uint32_t* dst = (isq ? g_qt : g_kt) + off;

    float2 cssn = g_csn[t * 32 + d];
    float e = src[d], o = src[d + 32];
    dst[d]      = f2tf(e * cssn.x - o * cssn.y);
    dst[d + 32] = f2tf(e * cssn.y + o * cssn.x);
    dst[d + 64] = f2tf(src[d + 64]);
    dst[d + 96] = f2tf(src[d + 96]);
}

// ---------------------------------------------------------------------------
// Tensor-core flash attention, Br=128, Bc=64, 8 warps (256 thr).
// Q reg-resident; split cp.async groups (K overlaps softmax+PV, V overlaps S).
// exp2 online softmax; reverse qblk order; tf32 out.
// ---------------------------------------------------------------------------
#define KSP 132
#define VSP 136
#define PSP 72
#define K_WORDS (64 * KSP)                     // 8448
#define V_WORDS (64 * VSP)                     // 8704
#define P_WORDS (128 * PSP)                    // 9216
#define ATTN_SMEM_BYTES ((K_WORDS + V_WORDS + P_WORDS) * 4)  // 105472

__global__ void __launch_bounds__(256, 1) attn_mma()
{
    extern __shared__ uint32_t smu[];
    uint32_t* KQ = smu;                        // K tiles [64][132]; Q staging [128][132]
    uint32_t* Vs = smu + K_WORDS;              // [64][136]
    uint32_t* Ps = smu + K_WORDS + V_WORDS;    // [128][72]

    const int qblk = gridDim.x - 1 - blockIdx.x;   // longest first
    const int bh   = blockIdx.y;
    const uint32_t* Qg = g_qt + (size_t)bh * T_ * D_ + (size_t)qblk * 128 * D_;
    const uint32_t* Kg = g_kt + (size_t)bh * T_ * D_;
    const uint32_t* Vg = g_vt + (size_t)bh * T_ * D_;

    const int tid  = threadIdx.x;
    const int lane = tid & 31;
    const int wr   = tid >> 5;                 // 0..7, warp owns rows wr*16..+15
    const int g    = lane >> 2;
    const int lq   = lane & 3;

    const uint32_t kqB = (uint32_t)__cvta_generic_to_shared(KQ);
    const uint32_t vsB = (uint32_t)__cvta_generic_to_shared(Vs);

    auto issueK = [&](int jt) {
#pragma unroll
        for (int it = 0; it < 8; it++) {
            int idx = tid + it * 256;
            int r = idx >> 5, d4 = idx & 31;
            cp16(kqB + (r * KSP + 4 * d4) * 4,
                 Kg + (size_t)(jt * 64 + r) * D_ + 4 * d4);
        }
        CP_COMMIT();
    };
    auto issueV = [&](int jt) {
#pragma unroll
        for (int it = 0; it < 8; it++) {
            int idx = tid + it * 256;
            int r = idx >> 5, d4 = idx & 31;
            cp16(vsB + (r * VSP + 4 * d4) * 4,
                 Vg + (size_t)(jt * 64 + r) * D_ + 4 * d4);
        }
        CP_COMMIT();
    };

    // ---- stage Q (128x128) across K+V regions, pitch 132 ----
#pragma unroll
    for (int it = 0; it < 16; it++) {
        int idx = tid + it * 256;
        int r = idx >> 5, d4 = idx & 31;
        cp16(kqB + (r * KSP + 4 * d4) * 4, Qg + (size_t)r * D_ + 4 * d4);
    }
    CP_COMMIT();
    CP_WAIT(0);
    __syncthreads();

    uint32_t qfr[16][4];
#pragma unroll
    for (int ks = 0; ks < 16; ks++) {
        const uint32_t* p = &KQ[(wr * 16 + g) * KSP + 8 * ks + lq];
        qfr[ks][0] = p[0];
        qfr[ks][1] = p[8 * KSP];
        qfr[ks][2] = p[4];
        qfr[ks][3] = p[8 * KSP + 4];
    }
    __syncthreads();   // all warps done reading Q before K(0)/V(0) overwrite

    issueK(0);
    issueV(0);
    CP_WAIT(0);
    __syncthreads();

    float oacc[16][4];
#pragma unroll
    for (int nf = 0; nf < 16; nf++)
#pragma unroll
        for (int e = 0; e < 4; e++) oacc[nf][e] = 0.0f;
    float mrow[2] = { -1e30f, -1e30f };
    float lrow[2] = { 0.0f, 0.0f };

    const float Kc = 1.44269504f / 128.0f;
    const int jend = 2 * qblk + 1;

    for (int jt = 0; jt <= jend; jt++) {
        // invariant: K(jt) visible; V(jt) is oldest pending group (or visible)

        // ---- S = Q K^T ----
        float sacc[8][4];
#pragma unroll
        for (int nf = 0; nf < 8; nf++)
#pragma unroll
            for (int e = 0; e < 4; e++) sacc[nf][e] = 0.0f;

#pragma unroll
        for (int ks = 0; ks < 16; ks++) {
            uint32_t bfr[8][2];
#pragma unroll
            for (int nf = 0; nf < 8; nf++) {
                const uint32_t* p = &KQ[(8 * nf + g) * KSP + 8 * ks + lq];
                bfr[nf][0] = p[0];
                bfr[nf][1] = p[4];
            }
#pragma unroll
            for (int nf = 0; nf < 8; nf++)
                mma_tf32(sacc[nf], qfr[ks], bfr[nf]);
        }

        __syncthreads();                 // all warps done reading K(jt)
        if (jt < jend) issueK(jt + 1);   // overlaps softmax + PV

        // ---- softmax (exp2 domain) ----
#pragma unroll
        for (int nf = 0; nf < 8; nf++)
#pragma unroll
            for (int e = 0; e < 4; e++) sacc[nf][e] *= Kc;

        if (jt >= 2 * qblk) {            // diagonal band: mask
#pragma unroll
            for (int nf = 0; nf < 8; nf++)
#pragma unroll
                for (int e = 0; e < 4; e++) {
                    int col = jt * 64 + nf * 8 + 2 * lq + (e & 1);
                    int row = qblk * 128 + wr * 16 + g + (e >> 1) * 8;
                    if (col > row) sacc[nf][e] = -1e30f;
                }
        }

        float zmax[2] = { -1e30f, -1e30f };
#pragma unroll
        for (int nf = 0; nf < 8; nf++) {
            zmax[0] = fmaxf(zmax[0], fmaxf(sacc[nf][0], sacc[nf][1]));
            zmax[1] = fmaxf(zmax[1], fmaxf(sacc[nf][2], sacc[nf][3]));
        }
#pragma unroll
        for (int off = 1; off <= 2; off <<= 1) {
            zmax[0] = fmaxf(zmax[0], __shfl_xor_sync(0xffffffffu, zmax[0], off));
            zmax[1] = fmaxf(zmax[1], __shfl_xor_sync(0xffffffffu, zmax[1], off));
        }

        float alpha[2], psum[2] = { 0.0f, 0.0f };
#pragma unroll
        for (int rr = 0; rr < 2; rr++) {
            float mn = fmaxf(mrow[rr], zmax[rr]);
            alpha[rr] = ex2(mrow[rr] - mn);
            mrow[rr] = mn;
        }
#pragma unroll
        for (int nf = 0; nf < 8; nf++) {
            float p0 = ex2(sacc[nf][0] - mrow[0]);
            float p1 = ex2(sacc[nf][1] - mrow[0]);
            float p2 = ex2(sacc[nf][2] - mrow[1]);
            float p3 = ex2(sacc[nf][3] - mrow[1]);
            sacc[nf][0] = p0; sacc[nf][1] = p1;
            sacc[nf][2] = p2; sacc[nf][3] = p3;
            psum[0] += p0 + p1;
            psum[1] += p2 + p3;
        }
#pragma unroll
        for (int off = 1; off <= 2; off <<= 1) {
            psum[0] += __shfl_xor_sync(0xffffffffu, psum[0], off);
            psum[1] += __shfl_xor_sync(0xffffffffu, psum[1], off);
        }
        lrow[0] = lrow[0] * alpha[0] + psum[0];
        lrow[1] = lrow[1] * alpha[1] + psum[1];
#pragma unroll
        for (int nf = 0; nf < 16; nf++) {
            oacc[nf][0] *= alpha[0]; oacc[nf][1] *= alpha[0];
            oacc[nf][2] *= alpha[1]; oacc[nf][3] *= alpha[1];
        }

        // ---- P -> smem (warp-private rows) ----
#pragma unroll
        for (int nf = 0; nf < 8; nf++) {
            uint2 u0 = make_uint2(f2tf(sacc[nf][0]), f2tf(sacc[nf][1]));
            uint2 u1 = make_uint2(f2tf(sacc[nf][2]), f2tf(sacc[nf][3]));
            *(uint2*)&Ps[(wr * 16 + g) * PSP + 8 * nf + 2 * lq] = u0;
            *(uint2*)&Ps[(wr * 16 + g + 8) * PSP + 8 * nf + 2 * lq] = u1;
        }
        __syncwarp();

        // ---- ensure V(jt) visible ----
        if (jt < jend) { CP_WAIT(1); } else { CP_WAIT(0); }
        __syncthreads();

        // ---- O += P V ----
#pragma unroll
        for (int ks = 0; ks < 8; ks++) {
            uint32_t pfr[4];
            const uint32_t* pp = &Ps[(wr * 16 + g) * PSP + 8 * ks + lq];
            pfr[0] = pp[0];
            pfr[1] = pp[8 * PSP];
            pfr[2] = pp[4];
            pfr[3] = pp[8 * PSP + 4];
#pragma unroll
            for (int nf = 0; nf < 16; nf++) {
                uint32_t vfr[2];
                const uint32_t* vp = &Vs[(8 * ks + lq) * VSP + 8 * nf + g];
                vfr[0] = vp[0];
                vfr[1] = vp[4 * VSP];
                mma_tf32(oacc[nf], pfr, vfr);
            }
        }

        __syncthreads();                 // all warps done reading V(jt)
        if (jt < jend) {
            issueV(jt + 1);              // overlaps S(jt+1)
            CP_WAIT(1);                  // K(jt+1) complete
        }
        __syncthreads();                 // K(jt+1) visible to all warps
    }

    // ---- epilogue: normalize, write tf32 into g_ot [B,T,H*D] ----
    const int b = bh >> 3, h = bh & 7;
    const float invl0 = 1.0f / lrow[0];
    const float invl1 = 1.0f / lrow[1];
    const int t0 = qblk * 128 + wr * 16 + g;
    uint32_t* dst0 = g_ot + ((size_t)(b * T_ + t0) * H_ + h) * D_;
    uint32_t* dst1 = g_ot + ((size_t)(b * T_ + t0 + 8) * H_ + h) * D_;
#pragma unroll
    for (int nf = 0; nf < 16; nf++) {
        int col = 8 * nf + 2 * lq;
        *(uint2*)(dst0 + col) = make_uint2(f2tf(oacc[nf][0] * invl0),
                                           f2tf(oacc[nf][1] * invl0));
        *(uint2*)(dst1 + col) = make_uint2(f2tf(oacc[nf][2] * invl1),
                                           f2tf(oacc[nf][3] * invl1));
    }
}

// ---------------------------------------------------------------------------
extern "C" void kernel_launch(void* const* d_in, const int* in_sizes, int n_in,
                              void* d_out, int out_size)
{
    const float* x  = (const float*)d_in[0];
    const float* wq = (const float*)d_in[1];
    const float* wk = (const float*)d_in[2];
    const float* wv = (const float*)d_in[3];
    const float* wo = (const float*)d_in[4];
    float* out = (float*)d_out;

    cudaFuncSetAttribute(gemm_cp<0>,
                         cudaFuncAttributeMaxDynamicSharedMemorySize, GEMM_SMEM_BYTES);
    cudaFuncSetAttribute(gemm_cp<1>,
                         cudaFuncAttributeMaxDynamicSharedMemorySize, GEMM_SMEM_BYTES);
    cudaFuncSetAttribute(attn_mma,
                         cudaFuncAttributeMaxDynamicSharedMemorySize, ATTN_SMEM_BYTES);

    // tf32 pre-conversion + rope table
    conv_x<<<4096, 256>>>(x);
    conv_w<<<dim3(1024, 4), 256>>>(wq, wk, wv, wo);
    csn_kernel<<<256, 256>>>();

    // QKV projection (q,k -> f32; v -> tf32); CTA tile 128x256
    gemm_cp<0><<<dim3(4, 32, 3), 256, GEMM_SMEM_BYTES>>>(nullptr);

    // Fractional RoPE (table-based): q,k -> tf32 g_qt/g_kt
    rope_kernel<<<dim3(T_ / 4, BH_), 256>>>();

    // Tensor-core flash attention (Br=128, pipelined)
    attn_mma<<<dim3(T_ / 128, BH_), 256, ATTN_SMEM_BYTES>>>();

    // Output projection
    gemm_cp<1><<<dim3(4, 32), 256, GEMM_SMEM_BYTES>>>(out);
}

// round 10
// speedup vs baseline: 1.0349x; 1.0349x over previous
#include <cuda_runtime.h>
#include <cstdint>
#include <math.h>

#define B_ 2
#define T_ 2048
#define M_ 1024
#define H_ 8
#define D_ 128
#define BH_ (B_*H_)

// Scratch (allocation-free: device globals)
__device__ float    g_q[BH_ * T_ * D_];        // [B,H,T,D] f32 (pre-rope)
__device__ float    g_k[BH_ * T_ * D_];        // [B,H,T,D] f32 (pre-rope)
__device__ uint32_t g_qt[BH_ * T_ * D_];       // tf32 q (post-rope, pre-scaled)
__device__ uint32_t g_kt[BH_ * T_ * D_];       // tf32 k (post-rope)
__device__ uint32_t g_vt[BH_ * T_ * D_];       // tf32 v
__device__ uint32_t g_ot[B_ * T_ * H_ * D_];   // [B,T,H*D] tf32 (attention out)
__device__ uint32_t g_xt[B_ * T_ * M_];        // tf32(x)
__device__ uint32_t g_wtf[4 * M_ * M_];        // tf32(wq,wk,wv,wo)
__device__ float2   g_csn[T_ * 32];            // rope cos/sin table

__device__ __forceinline__ uint32_t f2tf(float x) {
    uint32_t r;
    asm("cvt.rna.tf32.f32 %0, %1;" : "=r"(r) : "f"(x));
    return r;
}
__device__ __forceinline__ float ex2(float x) {
    float r;
    asm("ex2.approx.ftz.f32 %0, %1;" : "=f"(r) : "f"(x));
    return r;
}
__device__ __forceinline__ void mma_tf32(float c[4], const uint32_t a[4],
                                         const uint32_t b[2]) {
    asm volatile(
        "mma.sync.aligned.m16n8k8.row.col.f32.tf32.tf32.f32 "
        "{%0,%1,%2,%3}, {%4,%5,%6,%7}, {%8,%9}, {%0,%1,%2,%3};"
        : "+f"(c[0]), "+f"(c[1]), "+f"(c[2]), "+f"(c[3])
        : "r"(a[0]), "r"(a[1]), "r"(a[2]), "r"(a[3]), "r"(b[0]), "r"(b[1]));
}
__device__ __forceinline__ void cp16(uint32_t smem_dst, const void* gptr) {
    asm volatile("cp.async.cg.shared.global [%0], [%1], 16;"
                 :: "r"(smem_dst), "l"(gptr));
}
#define CP_COMMIT() asm volatile("cp.async.commit_group;" ::: "memory")
#define CP_WAIT(n)  asm volatile("cp.async.wait_group %0;" :: "n"(n) : "memory")

// ---------------------------------------------------------------------------
// tf32 pre-conversion + rope table
// ---------------------------------------------------------------------------
__global__ void conv_x(const float* __restrict__ x)
{
    int i = blockIdx.x * 256 + threadIdx.x;
    float4 v = ((const float4*)x)[i];
    ((uint4*)g_xt)[i] = make_uint4(f2tf(v.x), f2tf(v.y), f2tf(v.z), f2tf(v.w));
}
__global__ void conv_w(const float* __restrict__ wq, const float* __restrict__ wk,
                       const float* __restrict__ wv, const float* __restrict__ wo)
{
    const float* src = (blockIdx.y == 0) ? wq : (blockIdx.y == 1) ? wk
                     : (blockIdx.y == 2) ? wv : wo;
    uint4* dst = (uint4*)(g_wtf + (size_t)blockIdx.y * M_ * M_);
    int i = blockIdx.x * 256 + threadIdx.x;
    float4 v = ((const float4*)src)[i];
    dst[i] = make_uint4(f2tf(v.x), f2tf(v.y), f2tf(v.z), f2tf(v.w));
}
__global__ void csn_kernel()
{
    int i = blockIdx.x * 256 + threadIdx.x;     // 65536 total
    int t = i >> 5, d = i & 31;
    float freq = powf(10000.0f, -(float)d * (1.0f / 32.0f));
    float sn, cs;
    sincosf((float)t * freq, &sn, &cs);
    g_csn[i] = make_float2(cs, sn);
}

// ---------------------------------------------------------------------------
// tf32 mma.sync GEMM, 3-stage cp.async (R8 config: CTA 128x128, 8 warps,
// warp tile 64x32, K-chunk 32, 2 CTAs/SM).
// MODE 0: A = g_xt, W = g_wtf[z]; z=0,1 -> f32 g_q/g_k; z=2 -> tf32 g_vt.
// MODE 1: A = g_ot, W = g_wtf[3], f32 row-major store to Cout.
// ---------------------------------------------------------------------------
#define AP 36
#define BP 136
#define AS_WORDS (128 * AP)
#define BS_WORDS (32 * BP)
#define STG_WORDS (AS_WORDS + BS_WORDS)
#define GEMM_SMEM_BYTES (3 * STG_WORDS * 4)    // 107520

template <int MODE>
__global__ void __launch_bounds__(256, 2) gemm_cp(float* __restrict__ Cout)
{
    extern __shared__ uint32_t smw[];

    const uint32_t* Ap;
    const uint32_t* W;
    if (MODE == 0) {
        Ap = g_xt;
        W  = g_wtf + (size_t)blockIdx.z * M_ * M_;
    } else {
        Ap = g_ot;
        W  = g_wtf + (size_t)3 * M_ * M_;
    }

    const int tid  = threadIdx.x;
    const int lane = tid & 31;
    const int wid  = tid >> 5;
    const int wm   = wid & 1;
    const int wn   = wid >> 1;
    const int g    = lane >> 2;
    const int lq   = lane & 3;

    const int r0 = blockIdx.y * 128;
    const int c0 = blockIdx.x * 128;

    const uint32_t smbase = (uint32_t)__cvta_generic_to_shared(smw);

    auto issue = [&](int c) {
        const int s = c % 3;
        const uint32_t aB = smbase + s * STG_WORDS * 4;
        const uint32_t bB = aB + AS_WORDS * 4;
        const int kc = c * 32;
#pragma unroll
        for (int it = 0; it < 4; it++) {
            int idx = tid + it * 256;
            int r = idx >> 3, k4 = idx & 7;
            cp16(aB + (r * AP + 4 * k4) * 4,
                 Ap + (size_t)(r0 + r) * 1024 + kc + 4 * k4);
            int k = idx >> 5, n4 = idx & 31;
            cp16(bB + (k * BP + 4 * n4) * 4,
                 W + (size_t)(kc + k) * 1024 + c0 + 4 * n4);
        }
        CP_COMMIT();
    };

    float acc[4][4][4];
#pragma unroll
    for (int i = 0; i < 4; i++)
#pragma unroll
        for (int j = 0; j < 4; j++)
#pragma unroll
            for (int e = 0; e < 4; e++) acc[i][j][e] = 0.0f;

    issue(0);
    issue(1);

    for (int c = 0; c < 32; c++) {
        if (c < 30) { CP_WAIT(1); } else { CP_WAIT(0); }
        __syncthreads();

        const uint32_t* As = smw + (c % 3) * STG_WORDS;
        const uint32_t* Bs = As + AS_WORDS;

#pragma unroll
        for (int ks = 0; ks < 4; ks++) {
            const int kk = ks * 8;
            uint32_t afr[4][4];
#pragma unroll
            for (int mf = 0; mf < 4; mf++) {
                const uint32_t* p = &As[(wm * 64 + mf * 16 + g) * AP + kk + lq];
                afr[mf][0] = p[0];
                afr[mf][1] = p[8 * AP];
                afr[mf][2] = p[4];
                afr[mf][3] = p[8 * AP + 4];
            }
            uint32_t bfr[4][2];
#pragma unroll
            for (int nf = 0; nf < 4; nf++) {
                const uint32_t* p = &Bs[(kk + lq) * BP + wn * 32 + nf * 8 + g];
                bfr[nf][0] = p[0];
                bfr[nf][1] = p[4 * BP];
            }
#pragma unroll
            for (int mf = 0; mf < 4; mf++)
#pragma unroll
                for (int nf = 0; nf < 4; nf++)
                    mma_tf32(acc[mf][nf], afr[mf], bfr[nf]);
        }

        if (c + 2 < 32) issue(c + 2);
    }

#pragma unroll
    for (int mf = 0; mf < 4; mf++) {
#pragma unroll
        for (int half = 0; half < 2; half++) {
            int row = r0 + wm * 64 + mf * 16 + g + half * 8;
#pragma unroll
            for (int nf = 0; nf < 4; nf++) {
                int col = wn * 32 + nf * 8 + 2 * lq;
                float v0 = half ? acc[mf][nf][2] : acc[mf][nf][0];
                float v1 = half ? acc[mf][nf][3] : acc[mf][nf][1];
                if (MODE == 0) {
                    int bb = row >> 11, t = row & 2047;
                    size_t off = ((size_t)(bb * H_ + blockIdx.x) * T_ + t) * D_ + col;
                    if (blockIdx.z == 2) {
                        *(uint2*)(g_vt + off) = make_uint2(f2tf(v0), f2tf(v1));
                    } else {
                        float* O = (blockIdx.z == 0) ? g_q : g_k;
                        *(float2*)(O + off) = make_float2(v0, v1);
                    }
                } else {
                    *(float2*)(Cout + (size_t)row * 1024 + c0 + col) =
                        make_float2(v0, v1);
                }
            }
        }
    }
}

// ---------------------------------------------------------------------------
// Fractional RoPE via table. Q additionally pre-scaled by log2(e)/128 so the
// attention S matrix comes out directly in exp2 domain.
// ---------------------------------------------------------------------------
#define KC_ (1.44269504f / 128.0f)

__global__ void rope_kernel()
{
    const int t  = blockIdx.x * 4 + (threadIdx.x >> 6);
    const int bh = blockIdx.y;
    const int r  = threadIdx.x & 63;
    const int d  = r & 31;
    const bool isq = (r < 32);
    const size_t off = ((size_t)bh * T_ + t) * D_;
    const float* src = (isq ? g_q : g_k) + off;
    uint32_t* dst = (isq ? g_qt : g_kt) + off;
    const float sc = isq ? KC_ : 1.0f;

    float2 cssn = g_csn[t * 32 + d];
    float e = src[d], o = src[d + 32];
    dst[d]      = f2tf((e * cssn.x - o * cssn.y) * sc);
    dst[d + 32] = f2tf((e * cssn.y + o * cssn.x) * sc);
    dst[d + 64] = f2tf(src[d + 64] * sc);
    dst[d + 96] = f2tf(src[d + 96] * sc);
}

// ---------------------------------------------------------------------------
// Tensor-core flash attention (R8 config: Br=Bc=64, 4 warps, 2 CTAs/SM),
// with merged syncs (3/iter) and ballot-gated alpha rescale.
// Q pre-scaled -> S is already in exp2 domain.
// ---------------------------------------------------------------------------
#define KSP 132
#define VSP 136
#define PSP 72
#define KQ_WORDS (64 * KSP)
#define ATTN_SMEM_BYTES ((KQ_WORDS + 64 * VSP + 64 * PSP) * 4) // 87296

__global__ void __launch_bounds__(128) attn_mma()
{
    extern __shared__ uint32_t smu[];
    uint32_t* KQ = smu;                      // Q stage then K tiles [64][132]
    uint32_t* Vs = smu + KQ_WORDS;           // [64][136]
    uint32_t* Ps = Vs + 64 * VSP;            // [64][72]

    const int qblk = gridDim.x - 1 - blockIdx.x;   // longest first
    const int bh   = blockIdx.y;
    const uint32_t* Qg = g_qt + (size_t)bh * T_ * D_ + (size_t)qblk * 64 * D_;
    const uint32_t* Kg = g_kt + (size_t)bh * T_ * D_;
    const uint32_t* Vg = g_vt + (size_t)bh * T_ * D_;

    const int tid  = threadIdx.x;
    const int lane = tid & 31;
    const int wr   = tid >> 5;
    const int g    = lane >> 2;
    const int lq   = lane & 3;

    const uint32_t kqB = (uint32_t)__cvta_generic_to_shared(KQ);
    const uint32_t vsB = (uint32_t)__cvta_generic_to_shared(Vs);

    auto issueK = [&](int jt) {
#pragma unroll
        for (int it = 0; it < 16; it++) {
            int idx = tid + it * 128;
            int r = idx >> 5, d4 = idx & 31;
            cp16(kqB + (r * KSP + 4 * d4) * 4,
                 Kg + (size_t)(jt * 64 + r) * D_ + 4 * d4);
        }
        CP_COMMIT();
    };
    auto issueV = [&](int jt) {
#pragma unroll
        for (int it = 0; it < 16; it++) {
            int idx = tid + it * 128;
            int r = idx >> 5, d4 = idx & 31;
            cp16(vsB + (r * VSP + 4 * d4) * 4,
                 Vg + (size_t)(jt * 64 + r) * D_ + 4 * d4);
        }
        CP_COMMIT();
    };

    // ---- stage Q, load register fragments ----
#pragma unroll
    for (int it = 0; it < 16; it++) {
        int idx = tid + it * 128;
        int r = idx >> 5, d4 = idx & 31;
        cp16(kqB + (r * KSP + 4 * d4) * 4, Qg + (size_t)r * D_ + 4 * d4);
    }
    CP_COMMIT();
    CP_WAIT(0);
    __syncthreads();

    uint32_t qfr[16][4];
#pragma unroll
    for (int ks = 0; ks < 16; ks++) {
        const uint32_t* p = &KQ[(wr * 16 + g) * KSP + 8 * ks + lq];
        qfr[ks][0] = p[0];
        qfr[ks][1] = p[8 * KSP];
        qfr[ks][2] = p[4];
        qfr[ks][3] = p[8 * KSP + 4];
    }
    __syncthreads();   // all warps done reading Q before K(0) overwrites

    issueK(0);
    issueV(0);
    CP_WAIT(0);
    __syncthreads();

    float oacc[16][4];
#pragma unroll
    for (int nf = 0; nf < 16; nf++)
#pragma unroll
        for (int e = 0; e < 4; e++) oacc[nf][e] = 0.0f;
    float mrow[2] = { -1e30f, -1e30f };
    float lrow[2] = { 0.0f, 0.0f };

    for (int jt = 0; jt <= qblk; jt++) {
        // invariant: K(jt), V(jt) visible in smem

        // ---- S = Q K^T (already exp2-domain: Q pre-scaled) ----
        float sacc[8][4];
#pragma unroll
        for (int nf = 0; nf < 8; nf++)
#pragma unroll
            for (int e = 0; e < 4; e++) sacc[nf][e] = 0.0f;

#pragma unroll
        for (int ks = 0; ks < 16; ks++) {
            uint32_t bfr[8][2];
#pragma unroll
            for (int nf = 0; nf < 8; nf++) {
                const uint32_t* p = &KQ[(8 * nf + g) * KSP + 8 * ks + lq];
                bfr[nf][0] = p[0];
                bfr[nf][1] = p[4];
            }
#pragma unroll
            for (int nf = 0; nf < 8; nf++)
                mma_tf32(sacc[nf], qfr[ks], bfr[nf]);
        }

        __syncthreads();                 // (1) all warps done reading K(jt)
        if (jt < qblk) issueK(jt + 1);   // overlaps softmax + PV

        // ---- softmax (exp2 domain) ----
        if (jt == qblk) {
#pragma unroll
            for (int nf = 0; nf < 8; nf++)
#pragma unroll
                for (int e = 0; e < 4; e++) {
                    int col = nf * 8 + 2 * lq + (e & 1);
                    int row = wr * 16 + g + (e >> 1) * 8;
                    if (col > row) sacc[nf][e] = -1e30f;
                }
        }

        float zmax[2] = { -1e30f, -1e30f };
#pragma unroll
        for (int nf = 0; nf < 8; nf++) {
            zmax[0] = fmaxf(zmax[0], fmaxf(sacc[nf][0], sacc[nf][1]));
            zmax[1] = fmaxf(zmax[1], fmaxf(sacc[nf][2], sacc[nf][3]));
        }
#pragma unroll
        for (int off = 1; off <= 2; off <<= 1) {
            zmax[0] = fmaxf(zmax[0], __shfl_xor_sync(0xffffffffu, zmax[0], off));
            zmax[1] = fmaxf(zmax[1], __shfl_xor_sync(0xffffffffu, zmax[1], off));
        }

        // ballot-gated alpha: skip rescale when no row raises its max
        bool need = (zmax[0] > mrow[0]) || (zmax[1] > mrow[1]);
        bool anyneed = __ballot_sync(0xffffffffu, need) != 0u;

        if (anyneed) {
            float alpha[2];
#pragma unroll
            for (int rr = 0; rr < 2; rr++) {
                float mn = fmaxf(mrow[rr], zmax[rr]);
                alpha[rr] = ex2(mrow[rr] - mn);
                mrow[rr] = mn;
            }
            lrow[0] *= alpha[0];
            lrow[1] *= alpha[1];
#pragma unroll
            for (int nf = 0; nf < 16; nf++) {
                oacc[nf][0] *= alpha[0]; oacc[nf][1] *= alpha[0];
                oacc[nf][2] *= alpha[1]; oacc[nf][3] *= alpha[1];
            }
        }

        float psum[2] = { 0.0f, 0.0f };
#pragma unroll
        for (int nf = 0; nf < 8; nf++) {
            float p0 = ex2(sacc[nf][0] - mrow[0]);
            float p1 = ex2(sacc[nf][1] - mrow[0]);
            float p2 = ex2(sacc[nf][2] - mrow[1]);
            float p3 = ex2(sacc[nf][3] - mrow[1]);
            sacc[nf][0] = p0; sacc[nf][1] = p1;
            sacc[nf][2] = p2; sacc[nf][3] = p3;
            psum[0] += p0 + p1;
            psum[1] += p2 + p3;
        }
#pragma unroll
        for (int off = 1; off <= 2; off <<= 1) {
            psum[0] += __shfl_xor_sync(0xffffffffu, psum[0], off);
            psum[1] += __shfl_xor_sync(0xffffffffu, psum[1], off);
        }
        lrow[0] += psum[0];
        lrow[1] += psum[1];

        // ---- P -> smem (warp-private) ----
#pragma unroll
        for (int nf = 0; nf < 8; nf++) {
            uint2 u0 = make_uint2(f2tf(sacc[nf][0]), f2tf(sacc[nf][1]));
            uint2 u1 = make_uint2(f2tf(sacc[nf][2]), f2tf(sacc[nf][3]));
            *(uint2*)&Ps[(wr * 16 + g) * PSP + 8 * nf + 2 * lq] = u0;
            *(uint2*)&Ps[(wr * 16 + g + 8) * PSP + 8 * nf + 2 * lq] = u1;
        }
        __syncwarp();

        // ---- O += P V (V(jt) already visible) ----
#pragma unroll
        for (int ks = 0; ks < 8; ks++) {
            uint32_t pfr[4];
            const uint32_t* pp = &Ps[(wr * 16 + g) * PSP + 8 * ks + lq];
            pfr[0] = pp[0];
            pfr[1] = pp[8 * PSP];
            pfr[2] = pp[4];
            pfr[3] = pp[8 * PSP + 4];
#pragma unroll
            for (int nf = 0; nf < 16; nf++) {
                uint32_t vfr[2];
                const uint32_t* vp = &Vs[(8 * ks + lq) * VSP + 8 * nf + g];
                vfr[0] = vp[0];
                vfr[1] = vp[4 * VSP];
                mma_tf32(oacc[nf], pfr, vfr);
            }
        }

        // ---- merged tail: drain K(jt+1), ONE barrier, then refill V ----
        if (jt < qblk) {
            CP_WAIT(0);        // K(jt+1) done (this thread's groups)
            __syncthreads();   // (2+3 merged): V readers done + K(jt+1) visible
            issueV(jt + 1);    // overlaps S(jt+1); drained at next iter's sync
            CP_WAIT(0);        // V(jt+1) done before next PV (cheap: overlaps S via issue order? conservative)
            __syncthreads();   // V(jt+1) visible  -- keeps invariant simple
        }
    }

    // ---- epilogue: normalize, write tf32 into g_ot [B,T,H*D] ----
    const int b = bh >> 3, h = bh & 7;
    const float invl0 = 1.0f / lrow[0];
    const float invl1 = 1.0f / lrow[1];
    const int t0 = qblk * 64 + wr * 16 + g;
    uint32_t* dst0 = g_ot + ((size_t)(b * T_ + t0) * H_ + h) * D_;
    uint32_t* dst1 = g_ot + ((size_t)(b * T_ + t0 + 8) * H_ + h) * D_;
#pragma unroll
    for (int nf = 0; nf < 16; nf++) {
        int col = 8 * nf + 2 * lq;
        *(uint2*)(dst0 + col) = make_uint2(f2tf(oacc[nf][0] * invl0),
                                           f2tf(oacc[nf][1] * invl0));
        *(uint2*)(dst1 + col) = make_uint2(f2tf(oacc[nf][2] * invl1),
                                           f2tf(oacc[nf][3] * invl1));
    }
}

// ---------------------------------------------------------------------------
extern "C" void kernel_launch(void* const* d_in, const int* in_sizes, int n_in,
                              void* d_out, int out_size)
{
    const float* x  = (const float*)d_in[0];
    const float* wq = (const float*)d_in[1];
    const float* wk = (const float*)d_in[2];
    const float* wv = (const float*)d_in[3];
    const float* wo = (const float*)d_in[4];
    float* out = (float*)d_out;

    cudaFuncSetAttribute(gemm_cp<0>,
                         cudaFuncAttributeMaxDynamicSharedMemorySize, GEMM_SMEM_BYTES);
    cudaFuncSetAttribute(gemm_cp<1>,
                         cudaFuncAttributeMaxDynamicSharedMemorySize, GEMM_SMEM_BYTES);
    cudaFuncSetAttribute(attn_mma,
                         cudaFuncAttributeMaxDynamicSharedMemorySize, ATTN_SMEM_BYTES);

    // tf32 pre-conversion + rope table
    conv_x<<<4096, 256>>>(x);
    conv_w<<<dim3(1024, 4), 256>>>(wq, wk, wv, wo);
    csn_kernel<<<256, 256>>>();

    // QKV projection (q,k -> f32; v -> tf32); CTA tile 128x128
    gemm_cp<0><<<dim3(8, 32, 3), 256, GEMM_SMEM_BYTES>>>(nullptr);

    // Fractional RoPE (table-based, Q pre-scaled): q,k -> tf32 g_qt/g_kt
    rope_kernel<<<dim3(T_ / 4, BH_), 256>>>();

    // Tensor-core flash attention
    attn_mma<<<dim3(T_ / 64, BH_), 128, ATTN_SMEM_BYTES>>>();

    // Output projection
    gemm_cp<1><<<dim3(8, 32), 256, GEMM_SMEM_BYTES>>>(out);
}

// round 11
// speedup vs baseline: 1.8722x; 1.8092x over previous
#include <cuda_runtime.h>
#include <cuda_fp16.h>
#include <cstdint>
#include <math.h>

#define B_ 2
#define T_ 2048
#define M_ 1024
#define H_ 8
#define D_ 128
#define BH_ (B_*H_)

// Scratch (allocation-free: device globals)
__device__ float  g_q[BH_ * T_ * D_];          // f32 q pre-rope [b,h,t,d]
__device__ float  g_k[BH_ * T_ * D_];          // f32 k pre-rope [b,h,t,d]
__device__ __half g_qh[BH_ * T_ * D_];         // fp16 q post-rope, pre-scaled
__device__ __half g_kh[BH_ * T_ * D_];         // fp16 k post-rope
__device__ __half g_vh[BH_ * T_ * D_];         // fp16 v TRANSPOSED [b,h,d,t]
__device__ __half g_oh[B_ * T_ * M_];          // fp16 attention out [b,t,h*d]
__device__ __half g_xh[B_ * T_ * M_];          // fp16(x)
__device__ __half g_wh[4 * M_ * M_];           // fp16 W TRANSPOSED [z][n][k]
__device__ float2 g_csn[T_ * 32];              // rope cos/sin table

__device__ __forceinline__ float ex2(float x) {
    float r;
    asm("ex2.approx.ftz.f32 %0, %1;" : "=f"(r) : "f"(x));
    return r;
}
__device__ __forceinline__ uint32_t pk2(float a, float b) {
    __half2 h = __floats2half2_rn(a, b);
    return *(uint32_t*)&h;
}
__device__ __forceinline__ void mma16816(float c[4], const uint32_t a[4],
                                         const uint32_t b[2]) {
    asm volatile(
        "mma.sync.aligned.m16n8k16.row.col.f32.f16.f16.f32 "
        "{%0,%1,%2,%3}, {%4,%5,%6,%7}, {%8,%9}, {%0,%1,%2,%3};"
        : "+f"(c[0]), "+f"(c[1]), "+f"(c[2]), "+f"(c[3])
        : "r"(a[0]), "r"(a[1]), "r"(a[2]), "r"(a[3]), "r"(b[0]), "r"(b[1]));
}
__device__ __forceinline__ void ldsm4(uint32_t& r0, uint32_t& r1,
                                      uint32_t& r2, uint32_t& r3, uint32_t addr) {
    asm volatile("ldmatrix.sync.aligned.m8n8.x4.shared.b16 {%0,%1,%2,%3}, [%4];"
                 : "=r"(r0), "=r"(r1), "=r"(r2), "=r"(r3) : "r"(addr));
}
__device__ __forceinline__ void cp16(uint32_t smem_dst, const void* gptr) {
    asm volatile("cp.async.cg.shared.global [%0], [%1], 16;"
                 :: "r"(smem_dst), "l"(gptr));
}
#define CP_COMMIT() asm volatile("cp.async.commit_group;" ::: "memory")
#define CP_WAIT(n)  asm volatile("cp.async.wait_group %0;" :: "n"(n) : "memory")

// ---------------------------------------------------------------------------
// fp16 pre-conversion + rope table
// ---------------------------------------------------------------------------
__global__ void conv_x(const float* __restrict__ x)
{
    int i = blockIdx.x * 256 + threadIdx.x;          // float4 index (1M total)
    float4 v = ((const float4*)x)[i];
    ((uint2*)g_xh)[i] = make_uint2(pk2(v.x, v.y), pk2(v.z, v.w));
}
// W transpose: g_wh[z][n][k] = fp16(W_z[k][n])
__global__ void conv_w(const float* __restrict__ wq, const float* __restrict__ wk,
                       const float* __restrict__ wv, const float* __restrict__ wo)
{
    __shared__ __half t[32][33];
    const int z = blockIdx.z;
    const float* src = (z == 0) ? wq : (z == 1) ? wk : (z == 2) ? wv : wo;
    __half* dst = g_wh + (size_t)z * M_ * M_;

    int x = blockIdx.x * 32 + threadIdx.x;    // n
    int y = blockIdx.y * 32 + threadIdx.y;    // k
#pragma unroll
    for (int i = 0; i < 32; i += 8)
        t[threadIdx.y + i][threadIdx.x] = __float2half_rn(src[(size_t)(y + i) * 1024 + x]);
    __syncthreads();
    int xn = blockIdx.x * 32, yk = blockIdx.y * 32;
#pragma unroll
    for (int i = 0; i < 32; i += 8)
        dst[(size_t)(xn + threadIdx.y + i) * 1024 + yk + threadIdx.x] =
            t[threadIdx.x][threadIdx.y + i];
}
__global__ void csn_kernel()
{
    int i = blockIdx.x * 256 + threadIdx.x;     // 65536 total
    int t = i >> 5, d = i & 31;
    float freq = powf(10000.0f, -(float)d * (1.0f / 32.0f));
    float sn, cs;
    sincosf((float)t * freq, &sn, &cs);
    g_csn[i] = make_float2(cs, sn);
}

// ---------------------------------------------------------------------------
// fp16 mma.sync GEMM: CTA 128x128, 8 warps (2m x 4n), warp 64x32, K-chunk 64,
// 3-stage cp.async, ldmatrix.x4 fragments. A [m][k], B (=W^T) [n][k].
// MODE 0: A = g_xh, W = g_wh[z]; z=0,1 -> f32 g_q/g_k [b,h,t,d];
//         z=2 -> fp16 g_vh TRANSPOSED [b,h,d,t].
// MODE 1: A = g_oh, W = g_wh[3], f32 row-major store to Cout.
// ---------------------------------------------------------------------------
#define APH 72     // A smem pitch (fp16)
#define BPH 72     // B smem pitch (fp16)
#define A_BYTES (128 * APH * 2)                // 18432
#define B_BYTES (128 * BPH * 2)                // 18432
#define STG_BYTES (A_BYTES + B_BYTES)          // 36864
#define GEMM_SMEM_BYTES (3 * STG_BYTES)        // 110592

template <int MODE>
__global__ void __launch_bounds__(256, 2) gemm_cp(float* __restrict__ Cout)
{
    extern __shared__ __half smh[];

    const __half* Ap;
    const __half* Wt;
    if (MODE == 0) {
        Ap = g_xh;
        Wt = g_wh + (size_t)blockIdx.z * M_ * M_;
    } else {
        Ap = g_oh;
        Wt = g_wh + (size_t)3 * M_ * M_;
    }

    const int tid  = threadIdx.x;
    const int lane = tid & 31;
    const int wid  = tid >> 5;
    const int wm   = wid & 1;
    const int wn   = wid >> 1;
    const int g    = lane >> 2;
    const int lq   = lane & 3;

    const int r0 = blockIdx.y * 128;
    const int c0 = blockIdx.x * 128;

    const uint32_t smbase = (uint32_t)__cvta_generic_to_shared(smh);

    auto issue = [&](int c) {
        const uint32_t aB = smbase + (c % 3) * STG_BYTES;
        const uint32_t bB = aB + A_BYTES;
        const int kc = c * 64;
#pragma unroll
        for (int it = 0; it < 4; it++) {
            int idx = tid + it * 256;
            int r = idx >> 3, c8 = idx & 7;
            cp16(aB + (r * APH + 8 * c8) * 2,
                 Ap + (size_t)(r0 + r) * 1024 + kc + 8 * c8);
            cp16(bB + (r * BPH + 8 * c8) * 2,
                 Wt + (size_t)(c0 + r) * 1024 + kc + 8 * c8);
        }
        CP_COMMIT();
    };

    // ldmatrix per-lane coords
    const int lrowA = wm * 64 + (lane & 7) + ((lane >> 3) & 1) * 8;  // + mf*16
    const int lkA   = (lane >> 4) * 8;                               // + ks*16
    const int lrowB = wn * 32 + (lane & 7) + ((lane >> 4) << 3);     // + nf2*16
    const int lkB   = ((lane >> 3) & 1) * 8;                         // + ks*16

    float acc[4][4][4];
#pragma unroll
    for (int i = 0; i < 4; i++)
#pragma unroll
        for (int j = 0; j < 4; j++)
#pragma unroll
            for (int e = 0; e < 4; e++) acc[i][j][e] = 0.0f;

    issue(0);
    issue(1);

    for (int c = 0; c < 16; c++) {
        if (c < 14) { CP_WAIT(1); } else { CP_WAIT(0); }
        __syncthreads();

        const uint32_t aB = smbase + (c % 3) * STG_BYTES;
        const uint32_t bB = aB + A_BYTES;

#pragma unroll
        for (int ks = 0; ks < 4; ks++) {
            uint32_t afr[4][4];
#pragma unroll
            for (int mf = 0; mf < 4; mf++)
                ldsm4(afr[mf][0], afr[mf][1], afr[mf][2], afr[mf][3],
                      aB + ((lrowA + mf * 16) * APH + ks * 16 + lkA) * 2);
            uint32_t bfr[4][2];
#pragma unroll
            for (int nf2 = 0; nf2 < 2; nf2++)
                ldsm4(bfr[2 * nf2][0], bfr[2 * nf2][1],
                      bfr[2 * nf2 + 1][0], bfr[2 * nf2 + 1][1],
                      bB + ((lrowB + nf2 * 16) * BPH + ks * 16 + lkB) * 2);
#pragma unroll
            for (int mf = 0; mf < 4; mf++)
#pragma unroll
                for (int nf = 0; nf < 4; nf++)
                    mma16816(acc[mf][nf], afr[mf], bfr[nf]);
        }

        if (c + 2 < 16) issue(c + 2);
    }

    // ---- epilogue ----
#pragma unroll
    for (int mf = 0; mf < 4; mf++) {
#pragma unroll
        for (int half = 0; half < 2; half++) {
            int row = r0 + wm * 64 + mf * 16 + g + half * 8;
#pragma unroll
            for (int nf = 0; nf < 4; nf++) {
                int col = c0 + wn * 32 + nf * 8 + 2 * lq;
                float v0 = half ? acc[mf][nf][2] : acc[mf][nf][0];
                float v1 = half ? acc[mf][nf][3] : acc[mf][nf][1];
                if (MODE == 0) {
                    int bb = row >> 11, t = row & 2047;
                    int h = col >> 7, d = col & 127;
                    if (blockIdx.z == 2) {
                        // V transposed: [b,h,d,t] fp16
                        __half* dv = g_vh + ((size_t)(bb * H_ + h) * D_ + d) * T_ + t;
                        dv[0]  = __float2half_rn(v0);
                        dv[T_] = __float2half_rn(v1);
                    } else {
                        float* O = (blockIdx.z == 0) ? g_q : g_k;
                        *(float2*)(O + ((size_t)(bb * H_ + h) * T_ + t) * D_ + d) =
                            make_float2(v0, v1);
                    }
                } else {
                    *(float2*)(Cout + (size_t)row * 1024 + col) = make_float2(v0, v1);
                }
            }
        }
    }
}

// ---------------------------------------------------------------------------
// Fractional RoPE via table -> fp16; Q pre-scaled by log2(e)/128.
// ---------------------------------------------------------------------------
#define KC_ (1.44269504f / 128.0f)

__global__ void rope_kernel()
{
    const int t  = blockIdx.x * 4 + (threadIdx.x >> 6);
    const int bh = blockIdx.y;
    const int r  = threadIdx.x & 63;
    const int d  = r & 31;
    const bool isq = (r < 32);
    const size_t off = ((size_t)bh * T_ + t) * D_;
    const float* src = (isq ? g_q : g_k) + off;
    __half* dst = (isq ? g_qh : g_kh) + off;
    const float sc = isq ? KC_ : 1.0f;

    float2 cssn = g_csn[t * 32 + d];
    float e = src[d], o = src[d + 32];
    dst[d]      = __float2half_rn((e * cssn.x - o * cssn.y) * sc);
    dst[d + 32] = __float2half_rn((e * cssn.y + o * cssn.x) * sc);
    dst[d + 64] = __float2half_rn(src[d + 64] * sc);
    dst[d + 96] = __float2half_rn(src[d + 96] * sc);
}

// ---------------------------------------------------------------------------
// fp16 tensor-core flash attention: Br=Bc=64, 4 warps, K/V double-buffered,
// one combined KV cp.async group per step (full-iteration slack), 2 syncs/iter.
// Q fp16 pre-scaled -> S directly in exp2 domain. Reverse qblk order.
// smem: Ka,Kb [64][136] fp16; Va,Vb = V^T [128][72] fp16; Ps [64][72] fp16.
// ---------------------------------------------------------------------------
#define QKP 136
#define VTP 72
#define PSH 72
#define KA_OFF 0
#define KB_OFF 17408
#define VA_OFF 34816
#define VB_OFF 53248
#define PS_OFF 71680
#define ATTN_SMEM_BYTES 80896

__global__ void __launch_bounds__(128) attn_mma()
{
    extern __shared__ __half smh[];
    const uint32_t smbase = (uint32_t)__cvta_generic_to_shared(smh);
    const uint32_t kB[2] = { smbase + KA_OFF, smbase + KB_OFF };
    const uint32_t vB[2] = { smbase + VA_OFF, smbase + VB_OFF };
    const uint32_t psB   = smbase + PS_OFF;
    __half* PsH = smh + PS_OFF / 2;

    const int qblk = gridDim.x - 1 - blockIdx.x;   // longest first
    const int bh   = blockIdx.y;
    const __half* Qg = g_qh + ((size_t)bh * T_ + (size_t)qblk * 64) * D_;
    const __half* Kg = g_kh + (size_t)bh * T_ * D_;
    const __half* Vg = g_vh + (size_t)bh * D_ * T_;   // [d][t]

    const int tid  = threadIdx.x;
    const int lane = tid & 31;
    const int wr   = tid >> 5;
    const int g    = lane >> 2;
    const int lq   = lane & 3;

    // ldmatrix per-lane coords
    const int lrowQ = (lane & 7) + ((lane >> 3) & 1) * 8;   // + row base
    const int lkQ   = (lane >> 4) * 8;                      // + ks*16
    const int lrowB = (lane & 7) + ((lane >> 4) << 3);      // + nf2*16
    const int lkB   = ((lane >> 3) & 1) * 8;                // + ks*16

    auto issueKV = [&](int jt, int buf) {
        // K tile: 64 rows x 128 d  (16 chunks/row)
#pragma unroll
        for (int it = 0; it < 8; it++) {
            int idx = tid + it * 128;
            int r = idx >> 4, c8 = idx & 15;
            cp16(kB[buf] + (r * QKP + 8 * c8) * 2,
                 Kg + (size_t)(jt * 64 + r) * D_ + 8 * c8);
        }
        // V^T tile: 128 d-rows x 64 t (8 chunks/row)
#pragma unroll
        for (int it = 0; it < 8; it++) {
            int idx = tid + it * 128;
            int r = idx >> 3, c8 = idx & 7;
            cp16(vB[buf] + (r * VTP + 8 * c8) * 2,
                 Vg + (size_t)r * T_ + jt * 64 + 8 * c8);
        }
        CP_COMMIT();
    };

    // ---- stage Q into Ka, load register fragments ----
#pragma unroll
    for (int it = 0; it < 8; it++) {
        int idx = tid + it * 128;
        int r = idx >> 4, c8 = idx & 15;
        cp16(kB[0] + (r * QKP + 8 * c8) * 2, Qg + (size_t)r * D_ + 8 * c8);
    }
    CP_COMMIT();
    CP_WAIT(0);
    __syncthreads();

    uint32_t qfr[8][4];
#pragma unroll
    for (int ks = 0; ks < 8; ks++)
        ldsm4(qfr[ks][0], qfr[ks][1], qfr[ks][2], qfr[ks][3],
              kB[0] + ((wr * 16 + lrowQ) * QKP + ks * 16 + lkQ) * 2);
    __syncthreads();   // Q readers done before K(0) overwrites Ka

    issueKV(0, 0);
    if (qblk >= 1) issueKV(1, 1);
    if (qblk >= 1) { CP_WAIT(1); } else { CP_WAIT(0); }
    __syncthreads();

    float oacc[16][4];
#pragma unroll
    for (int nf = 0; nf < 16; nf++)
#pragma unroll
        for (int e = 0; e < 4; e++) oacc[nf][e] = 0.0f;
    float mrow[2] = { -1e30f, -1e30f };
    float lrow[2] = { 0.0f, 0.0f };

    for (int jt = 0; jt <= qblk; jt++) {
        const int buf = jt & 1;
        // invariant: K(jt), V(jt) visible in buf

        // ---- S = Q K^T (exp2-domain) ----
        float sacc[8][4];
#pragma unroll
        for (int nf = 0; nf < 8; nf++)
#pragma unroll
            for (int e = 0; e < 4; e++) sacc[nf][e] = 0.0f;

#pragma unroll
        for (int ks = 0; ks < 8; ks++) {
            uint32_t bfr[8][2];
#pragma unroll
            for (int nf2 = 0; nf2 < 4; nf2++)
                ldsm4(bfr[2 * nf2][0], bfr[2 * nf2][1],
                      bfr[2 * nf2 + 1][0], bfr[2 * nf2 + 1][1],
                      kB[buf] + ((nf2 * 16 + lrowB) * QKP + ks * 16 + lkB) * 2);
#pragma unroll
            for (int nf = 0; nf < 8; nf++)
                mma16816(sacc[nf], qfr[ks], bfr[nf]);
        }

        // ---- softmax ----
        if (jt == qblk) {
#pragma unroll
            for (int nf = 0; nf < 8; nf++)
#pragma unroll
                for (int e = 0; e < 4; e++) {
                    int col = nf * 8 + 2 * lq + (e & 1);
                    int row = wr * 16 + g + (e >> 1) * 8;
                    if (col > row) sacc[nf][e] = -1e30f;
                }
        }

        float zmax[2] = { -1e30f, -1e30f };
#pragma unroll
        for (int nf = 0; nf < 8; nf++) {
            zmax[0] = fmaxf(zmax[0], fmaxf(sacc[nf][0], sacc[nf][1]));
            zmax[1] = fmaxf(zmax[1], fmaxf(sacc[nf][2], sacc[nf][3]));
        }
#pragma unroll
        for (int off = 1; off <= 2; off <<= 1) {
            zmax[0] = fmaxf(zmax[0], __shfl_xor_sync(0xffffffffu, zmax[0], off));
            zmax[1] = fmaxf(zmax[1], __shfl_xor_sync(0xffffffffu, zmax[1], off));
        }

        float alpha[2], psum[2] = { 0.0f, 0.0f };
#pragma unroll
        for (int rr = 0; rr < 2; rr++) {
            float mn = fmaxf(mrow[rr], zmax[rr]);
            alpha[rr] = ex2(mrow[rr] - mn);
            mrow[rr] = mn;
        }
#pragma unroll
        for (int nf = 0; nf < 8; nf++) {
            float p0 = ex2(sacc[nf][0] - mrow[0]);
            float p1 = ex2(sacc[nf][1] - mrow[0]);
            float p2 = ex2(sacc[nf][2] - mrow[1]);
            float p3 = ex2(sacc[nf][3] - mrow[1]);
            sacc[nf][0] = p0; sacc[nf][1] = p1;
            sacc[nf][2] = p2; sacc[nf][3] = p3;
            psum[0] += p0 + p1;
            psum[1] += p2 + p3;
        }
#pragma unroll
        for (int off = 1; off <= 2; off <<= 1) {
            psum[0] += __shfl_xor_sync(0xffffffffu, psum[0], off);
            psum[1] += __shfl_xor_sync(0xffffffffu, psum[1], off);
        }
        lrow[0] = lrow[0] * alpha[0] + psum[0];
        lrow[1] = lrow[1] * alpha[1] + psum[1];
#pragma unroll
        for (int nf = 0; nf < 16; nf++) {
            oacc[nf][0] *= alpha[0]; oacc[nf][1] *= alpha[0];
            oacc[nf][2] *= alpha[1]; oacc[nf][3] *= alpha[1];
        }

        // ---- P -> smem fp16 (warp-private rows) ----
#pragma unroll
        for (int nf = 0; nf < 8; nf++) {
            *(uint32_t*)(PsH + (wr * 16 + g) * PSH + nf * 8 + 2 * lq) =
                pk2(sacc[nf][0], sacc[nf][1]);
            *(uint32_t*)(PsH + (wr * 16 + g + 8) * PSH + nf * 8 + 2 * lq) =
                pk2(sacc[nf][2], sacc[nf][3]);
        }
        __syncwarp();

        // ---- O += P V (fp16) ----
#pragma unroll
        for (int ks = 0; ks < 4; ks++) {
            uint32_t pfr[4];
            ldsm4(pfr[0], pfr[1], pfr[2], pfr[3],
                  psB + ((wr * 16 + lrowQ) * PSH + ks * 16 + lkQ) * 2);
            uint32_t vfr[2][2];
#pragma unroll
            for (int nf2 = 0; nf2 < 8; nf2++) {
                ldsm4(vfr[0][0], vfr[0][1], vfr[1][0], vfr[1][1],
                      vB[buf] + ((nf2 * 16 + lrowB) * VTP + ks * 16 + lkB) * 2);
                mma16816(oacc[2 * nf2],     pfr, vfr[0]);
                mma16816(oacc[2 * nf2 + 1], pfr, vfr[1]);
            }
        }

        __syncthreads();                      // all warps done with buf
        if (jt + 2 <= qblk) issueKV(jt + 2, buf);
        if (jt + 1 <= qblk) {
            if (jt + 2 <= qblk) { CP_WAIT(1); } else { CP_WAIT(0); }
            __syncthreads();                  // KV(jt+1) visible
        }
    }

    // ---- epilogue: normalize, write fp16 into g_oh [b,t,h*d] ----
    const int b = bh >> 3, h = bh & 7;
    const float invl0 = 1.0f / lrow[0];
    const float invl1 = 1.0f / lrow[1];
    const int t0 = qblk * 64 + wr * 16 + g;
    __half* dst0 = g_oh + (size_t)(b * T_ + t0) * M_ + h * D_;
    __half* dst1 = g_oh + (size_t)(b * T_ + t0 + 8) * M_ + h * D_;
#pragma unroll
    for (int nf = 0; nf < 16; nf++) {
        int col = 8 * nf + 2 * lq;
        *(uint32_t*)(dst0 + col) = pk2(oacc[nf][0] * invl0, oacc[nf][1] * invl0);
        *(uint32_t*)(dst1 + col) = pk2(oacc[nf][2] * invl1, oacc[nf][3] * invl1);
    }
}

// ---------------------------------------------------------------------------
extern "C" void kernel_launch(void* const* d_in, const int* in_sizes, int n_in,
                              void* d_out, int out_size)
{
    const float* x  = (const float*)d_in[0];
    const float* wq = (const float*)d_in[1];
    const float* wk = (const float*)d_in[2];
    const float* wv = (const float*)d_in[3];
    const float* wo = (const float*)d_in[4];
    float* out = (float*)d_out;

    cudaFuncSetAttribute(gemm_cp<0>,
                         cudaFuncAttributeMaxDynamicSharedMemorySize, GEMM_SMEM_BYTES);
    cudaFuncSetAttribute(gemm_cp<1>,
                         cudaFuncAttributeMaxDynamicSharedMemorySize, GEMM_SMEM_BYTES);
    cudaFuncSetAttribute(attn_mma,
                         cudaFuncAttributeMaxDynamicSharedMemorySize, ATTN_SMEM_BYTES);

    // fp16 pre-conversion (+W transpose) + rope table
    conv_x<<<4096, 256>>>(x);
    conv_w<<<dim3(32, 32, 4), dim3(32, 8)>>>(wq, wk, wv, wo);
    csn_kernel<<<256, 256>>>();

    // QKV projection (q,k -> f32; v -> fp16 transposed)
    gemm_cp<0><<<dim3(8, 32, 3), 256, GEMM_SMEM_BYTES>>>(nullptr);

    // Fractional RoPE (table-based, Q pre-scaled): q,k -> fp16
    rope_kernel<<<dim3(T_ / 4, BH_), 256>>>();

    // fp16 tensor-core flash attention
    attn_mma<<<dim3(T_ / 64, BH_), 128, ATTN_SMEM_BYTES>>>();

    // Output projection
    gemm_cp<1><<<dim3(8, 32), 256, GEMM_SMEM_BYTES>>>(out);
}

// round 12
// speedup vs baseline: 1.9747x; 1.0547x over previous
#include <cuda_runtime.h>
#include <cuda_fp16.h>
#include <cstdint>
#include <math.h>

#define B_ 2
#define T_ 2048
#define M_ 1024
#define H_ 8
#define D_ 128
#define BH_ (B_*H_)

// Scratch (allocation-free: device globals)
__device__ __half g_qh[BH_ * T_ * D_];         // fp16 q [b,h,t,d] (rope in-place)
__device__ __half g_kh[BH_ * T_ * D_];         // fp16 k [b,h,t,d] (rope in-place)
__device__ __half g_vh[BH_ * T_ * D_];         // fp16 v TRANSPOSED [b,h,d,t]
__device__ __half g_oh[B_ * T_ * M_];          // fp16 attention out [b,t,h*d]
__device__ __half g_xh[B_ * T_ * M_];          // fp16(x)
__device__ __half g_wh[4 * M_ * M_];           // fp16 W TRANSPOSED [z][n][k]
__device__ float2 g_csn[T_ * 32];              // rope cos/sin table

__device__ __forceinline__ float ex2(float x) {
    float r;
    asm("ex2.approx.ftz.f32 %0, %1;" : "=f"(r) : "f"(x));
    return r;
}
__device__ __forceinline__ uint32_t pk2(float a, float b) {
    __half2 h = __floats2half2_rn(a, b);
    return *(uint32_t*)&h;
}
__device__ __forceinline__ void mma16816(float c[4], const uint32_t a[4],
                                         const uint32_t b[2]) {
    asm volatile(
        "mma.sync.aligned.m16n8k16.row.col.f32.f16.f16.f32 "
        "{%0,%1,%2,%3}, {%4,%5,%6,%7}, {%8,%9}, {%0,%1,%2,%3};"
        : "+f"(c[0]), "+f"(c[1]), "+f"(c[2]), "+f"(c[3])
        : "r"(a[0]), "r"(a[1]), "r"(a[2]), "r"(a[3]), "r"(b[0]), "r"(b[1]));
}
__device__ __forceinline__ void ldsm4(uint32_t& r0, uint32_t& r1,
                                      uint32_t& r2, uint32_t& r3, uint32_t addr) {
    asm volatile("ldmatrix.sync.aligned.m8n8.x4.shared.b16 {%0,%1,%2,%3}, [%4];"
                 : "=r"(r0), "=r"(r1), "=r"(r2), "=r"(r3) : "r"(addr));
}
__device__ __forceinline__ void cp16(uint32_t smem_dst, const void* gptr) {
    asm volatile("cp.async.cg.shared.global [%0], [%1], 16;"
                 :: "r"(smem_dst), "l"(gptr));
}
#define CP_COMMIT() asm volatile("cp.async.commit_group;" ::: "memory")
#define CP_WAIT(n)  asm volatile("cp.async.wait_group %0;" :: "n"(n) : "memory")

// ---------------------------------------------------------------------------
// fp16 pre-conversion + rope table
// ---------------------------------------------------------------------------
__global__ void conv_x(const float* __restrict__ x)
{
    int i = blockIdx.x * 256 + threadIdx.x;          // float4 index (1M total)
    float4 v = ((const float4*)x)[i];
    ((uint2*)g_xh)[i] = make_uint2(pk2(v.x, v.y), pk2(v.z, v.w));
}
// W transpose: g_wh[z][n][k] = fp16(W_z[k][n])
__global__ void conv_w(const float* __restrict__ wq, const float* __restrict__ wk,
                       const float* __restrict__ wv, const float* __restrict__ wo)
{
    __shared__ __half t[32][33];
    const int z = blockIdx.z;
    const float* src = (z == 0) ? wq : (z == 1) ? wk : (z == 2) ? wv : wo;
    __half* dst = g_wh + (size_t)z * M_ * M_;

    int x = blockIdx.x * 32 + threadIdx.x;    // n
    int y = blockIdx.y * 32 + threadIdx.y;    // k
#pragma unroll
    for (int i = 0; i < 32; i += 8)
        t[threadIdx.y + i][threadIdx.x] = __float2half_rn(src[(size_t)(y + i) * 1024 + x]);
    __syncthreads();
    int xn = blockIdx.x * 32, yk = blockIdx.y * 32;
#pragma unroll
    for (int i = 0; i < 32; i += 8)
        dst[(size_t)(xn + threadIdx.y + i) * 1024 + yk + threadIdx.x] =
            t[threadIdx.x][threadIdx.y + i];
}
__global__ void csn_kernel()
{
    int i = blockIdx.x * 256 + threadIdx.x;     // 65536 total
    int t = i >> 5, d = i & 31;
    float freq = powf(10000.0f, -(float)d * (1.0f / 32.0f));
    float sn, cs;
    sincosf((float)t * freq, &sn, &cs);
    g_csn[i] = make_float2(cs, sn);
}

// ---------------------------------------------------------------------------
// fp16 mma.sync GEMM: CTA 128x128, 8 warps (2m x 4n), warp 64x32, K-chunk 64,
// 3-stage cp.async, ldmatrix.x4 fragments. A [m][k], B (=W^T) [n][k].
// MODE 0: A = g_xh, W = g_wh[z]; z=0,1 -> fp16 g_qh/g_kh [b,h,t,d];
//         z=2 -> fp16 g_vh TRANSPOSED [b,h,d,t].
// MODE 1: A = g_oh, W = g_wh[3], f32 row-major store to Cout.
// ---------------------------------------------------------------------------
#define APH 72
#define BPH 72
#define A_BYTES (128 * APH * 2)
#define B_BYTES (128 * BPH * 2)
#define STG_BYTES (A_BYTES + B_BYTES)          // 36864
#define GEMM_SMEM_BYTES (3 * STG_BYTES)        // 110592

template <int MODE>
__global__ void __launch_bounds__(256, 2) gemm_cp(float* __restrict__ Cout)
{
    extern __shared__ __half smh[];

    const __half* Ap;
    const __half* Wt;
    if (MODE == 0) {
        Ap = g_xh;
        Wt = g_wh + (size_t)blockIdx.z * M_ * M_;
    } else {
        Ap = g_oh;
        Wt = g_wh + (size_t)3 * M_ * M_;
    }

    const int tid  = threadIdx.x;
    const int lane = tid & 31;
    const int wid  = tid >> 5;
    const int wm   = wid & 1;
    const int wn   = wid >> 1;
    const int g    = lane >> 2;
    const int lq   = lane & 3;

    const int r0 = blockIdx.y * 128;
    const int c0 = blockIdx.x * 128;

    const uint32_t smbase = (uint32_t)__cvta_generic_to_shared(smh);

    auto issue = [&](int c) {
        const uint32_t aB = smbase + (c % 3) * STG_BYTES;
        const uint32_t bB = aB + A_BYTES;
        const int kc = c * 64;
#pragma unroll
        for (int it = 0; it < 4; it++) {
            int idx = tid + it * 256;
            int r = idx >> 3, c8 = idx & 7;
            cp16(aB + (r * APH + 8 * c8) * 2,
                 Ap + (size_t)(r0 + r) * 1024 + kc + 8 * c8);
            cp16(bB + (r * BPH + 8 * c8) * 2,
                 Wt + (size_t)(c0 + r) * 1024 + kc + 8 * c8);
        }
        CP_COMMIT();
    };

    const int lrowA = wm * 64 + (lane & 7) + ((lane >> 3) & 1) * 8;
    const int lkA   = (lane >> 4) * 8;
    const int lrowB = wn * 32 + (lane & 7) + ((lane >> 4) << 3);
    const int lkB   = ((lane >> 3) & 1) * 8;

    float acc[4][4][4];
#pragma unroll
    for (int i = 0; i < 4; i++)
#pragma unroll
        for (int j = 0; j < 4; j++)
#pragma unroll
            for (int e = 0; e < 4; e++) acc[i][j][e] = 0.0f;

    issue(0);
    issue(1);

    for (int c = 0; c < 16; c++) {
        if (c < 14) { CP_WAIT(1); } else { CP_WAIT(0); }
        __syncthreads();

        const uint32_t aB = smbase + (c % 3) * STG_BYTES;
        const uint32_t bB = aB + A_BYTES;

#pragma unroll
        for (int ks = 0; ks < 4; ks++) {
            uint32_t afr[4][4];
#pragma unroll
            for (int mf = 0; mf < 4; mf++)
                ldsm4(afr[mf][0], afr[mf][1], afr[mf][2], afr[mf][3],
                      aB + ((lrowA + mf * 16) * APH + ks * 16 + lkA) * 2);
            uint32_t bfr[4][2];
#pragma unroll
            for (int nf2 = 0; nf2 < 2; nf2++)
                ldsm4(bfr[2 * nf2][0], bfr[2 * nf2][1],
                      bfr[2 * nf2 + 1][0], bfr[2 * nf2 + 1][1],
                      bB + ((lrowB + nf2 * 16) * BPH + ks * 16 + lkB) * 2);
#pragma unroll
            for (int mf = 0; mf < 4; mf++)
#pragma unroll
                for (int nf = 0; nf < 4; nf++)
                    mma16816(acc[mf][nf], afr[mf], bfr[nf]);
        }

        if (c + 2 < 16) issue(c + 2);
    }

    // ---- epilogue ----
#pragma unroll
    for (int mf = 0; mf < 4; mf++) {
#pragma unroll
        for (int half = 0; half < 2; half++) {
            int row = r0 + wm * 64 + mf * 16 + g + half * 8;
#pragma unroll
            for (int nf = 0; nf < 4; nf++) {
                int col = c0 + wn * 32 + nf * 8 + 2 * lq;
                float v0 = half ? acc[mf][nf][2] : acc[mf][nf][0];
                float v1 = half ? acc[mf][nf][3] : acc[mf][nf][1];
                if (MODE == 0) {
                    int bb = row >> 11, t = row & 2047;
                    int h = col >> 7, d = col & 127;
                    if (blockIdx.z == 2) {
                        // V transposed: [b,h,d,t] fp16
                        __half* dv = g_vh + ((size_t)(bb * H_ + h) * D_ + d) * T_ + t;
                        dv[0]  = __float2half_rn(v0);
                        dv[T_] = __float2half_rn(v1);
                    } else {
                        __half* O = (blockIdx.z == 0) ? g_qh : g_kh;
                        *(uint32_t*)(O + ((size_t)(bb * H_ + h) * T_ + t) * D_ + d) =
                            pk2(v0, v1);
                    }
                } else {
                    *(float2*)(Cout + (size_t)row * 1024 + col) = make_float2(v0, v1);
                }
            }
        }
    }
}

// ---------------------------------------------------------------------------
// Fractional RoPE in-place on fp16 q/k; Q additionally pre-scaled by
// log2(e)/128 (all 128 dims). K: only the rotated 64 dims are rewritten.
// ---------------------------------------------------------------------------
#define KC_ (1.44269504f / 128.0f)

__global__ void rope_kernel()
{
    const int t  = blockIdx.x * 4 + (threadIdx.x >> 6);
    const int bh = blockIdx.y;
    const int r  = threadIdx.x & 63;
    const int d  = r & 31;
    const bool isq = (r < 32);
    __half* p = (isq ? g_qh : g_kh) + ((size_t)bh * T_ + t) * D_;

    float2 cssn = g_csn[t * 32 + d];
    float e = __half2float(p[d]), o = __half2float(p[d + 32]);
    if (isq) {
        p[d]      = __float2half_rn((e * cssn.x - o * cssn.y) * KC_);
        p[d + 32] = __float2half_rn((e * cssn.y + o * cssn.x) * KC_);
        p[d + 64] = __float2half_rn(__half2float(p[d + 64]) * KC_);
        p[d + 96] = __float2half_rn(__half2float(p[d + 96]) * KC_);
    } else {
        p[d]      = __float2half_rn(e * cssn.x - o * cssn.y);
        p[d + 32] = __float2half_rn(e * cssn.y + o * cssn.x);
    }
}

// ---------------------------------------------------------------------------
// fp16 flash attention: Br=Bc=64, 4 warps, K/V double-buffered cp.async,
// P passed in REGISTERS (S C-fragment == PV A-fragment layout), 2 syncs/iter.
// Q pre-scaled -> S directly in exp2 domain. Reverse qblk order.
// smem: Ka,Kb [64][136] fp16; Va,Vb = V^T [128][72] fp16.
// ---------------------------------------------------------------------------
#define QKP 136
#define VTP 72
#define KA_OFF 0
#define KB_OFF 17408
#define VA_OFF 34816
#define VB_OFF 53248
#define ATTN_SMEM_BYTES 71680

__global__ void __launch_bounds__(128) attn_mma()
{
    extern __shared__ __half smh[];
    const uint32_t smbase = (uint32_t)__cvta_generic_to_shared(smh);
    const uint32_t kB[2] = { smbase + KA_OFF, smbase + KB_OFF };
    const uint32_t vB[2] = { smbase + VA_OFF, smbase + VB_OFF };

    const int qblk = gridDim.x - 1 - blockIdx.x;   // longest first
    const int bh   = blockIdx.y;
    const __half* Qg = g_qh + ((size_t)bh * T_ + (size_t)qblk * 64) * D_;
    const __half* Kg = g_kh + (size_t)bh * T_ * D_;
    const __half* Vg = g_vh + (size_t)bh * D_ * T_;   // [d][t]

    const int tid  = threadIdx.x;
    const int lane = tid & 31;
    const int wr   = tid >> 5;
    const int g    = lane >> 2;
    const int lq   = lane & 3;

    const int lrowQ = (lane & 7) + ((lane >> 3) & 1) * 8;
    const int lkQ   = (lane >> 4) * 8;
    const int lrowB = (lane & 7) + ((lane >> 4) << 3);
    const int lkB   = ((lane >> 3) & 1) * 8;

    auto issueKV = [&](int jt, int buf) {
#pragma unroll
        for (int it = 0; it < 8; it++) {
            int idx = tid + it * 128;
            int r = idx >> 4, c8 = idx & 15;
            cp16(kB[buf] + (r * QKP + 8 * c8) * 2,
                 Kg + (size_t)(jt * 64 + r) * D_ + 8 * c8);
        }
#pragma unroll
        for (int it = 0; it < 8; it++) {
            int idx = tid + it * 128;
            int r = idx >> 3, c8 = idx & 7;
            cp16(vB[buf] + (r * VTP + 8 * c8) * 2,
                 Vg + (size_t)r * T_ + jt * 64 + 8 * c8);
        }
        CP_COMMIT();
    };

    // ---- stage Q into Ka, load register fragments ----
#pragma unroll
    for (int it = 0; it < 8; it++) {
        int idx = tid + it * 128;
        int r = idx >> 4, c8 = idx & 15;
        cp16(kB[0] + (r * QKP + 8 * c8) * 2, Qg + (size_t)r * D_ + 8 * c8);
    }
    CP_COMMIT();
    CP_WAIT(0);
    __syncthreads();

    uint32_t qfr[8][4];
#pragma unroll
    for (int ks = 0; ks < 8; ks++)
        ldsm4(qfr[ks][0], qfr[ks][1], qfr[ks][2], qfr[ks][3],
              kB[0] + ((wr * 16 + lrowQ) * QKP + ks * 16 + lkQ) * 2);
    __syncthreads();   // Q readers done before K(0) overwrites Ka

    issueKV(0, 0);
    if (qblk >= 1) issueKV(1, 1);
    if (qblk >= 1) { CP_WAIT(1); } else { CP_WAIT(0); }
    __syncthreads();

    float oacc[16][4];
#pragma unroll
    for (int nf = 0; nf < 16; nf++)
#pragma unroll
        for (int e = 0; e < 4; e++) oacc[nf][e] = 0.0f;
    float mrow[2] = { -1e30f, -1e30f };
    float lrow[2] = { 0.0f, 0.0f };

    for (int jt = 0; jt <= qblk; jt++) {
        const int buf = jt & 1;

        // ---- S = Q K^T (exp2-domain) ----
        float sacc[8][4];
#pragma unroll
        for (int nf = 0; nf < 8; nf++)
#pragma unroll
            for (int e = 0; e < 4; e++) sacc[nf][e] = 0.0f;

#pragma unroll
        for (int ks = 0; ks < 8; ks++) {
            uint32_t bfr[8][2];
#pragma unroll
            for (int nf2 = 0; nf2 < 4; nf2++)
                ldsm4(bfr[2 * nf2][0], bfr[2 * nf2][1],
                      bfr[2 * nf2 + 1][0], bfr[2 * nf2 + 1][1],
                      kB[buf] + ((nf2 * 16 + lrowB) * QKP + ks * 16 + lkB) * 2);
#pragma unroll
            for (int nf = 0; nf < 8; nf++)
                mma16816(sacc[nf], qfr[ks], bfr[nf]);
        }

        // ---- softmax ----
        if (jt == qblk) {
#pragma unroll
            for (int nf = 0; nf < 8; nf++)
#pragma unroll
                for (int e = 0; e < 4; e++) {
                    int col = nf * 8 + 2 * lq + (e & 1);
                    int row = wr * 16 + g + (e >> 1) * 8;
                    if (col > row) sacc[nf][e] = -1e30f;
                }
        }

        float zmax[2] = { -1e30f, -1e30f };
#pragma unroll
        for (int nf = 0; nf < 8; nf++) {
            zmax[0] = fmaxf(zmax[0], fmaxf(sacc[nf][0], sacc[nf][1]));
            zmax[1] = fmaxf(zmax[1], fmaxf(sacc[nf][2], sacc[nf][3]));
        }
#pragma unroll
        for (int off = 1; off <= 2; off <<= 1) {
            zmax[0] = fmaxf(zmax[0], __shfl_xor_sync(0xffffffffu, zmax[0], off));
            zmax[1] = fmaxf(zmax[1], __shfl_xor_sync(0xffffffffu, zmax[1], off));
        }

        float alpha[2], psum[2] = { 0.0f, 0.0f };
#pragma unroll
        for (int rr = 0; rr < 2; rr++) {
            float mn = fmaxf(mrow[rr], zmax[rr]);
            alpha[rr] = ex2(mrow[rr] - mn);
            mrow[rr] = mn;
        }
#pragma unroll
        for (int nf = 0; nf < 8; nf++) {
            float p0 = ex2(sacc[nf][0] - mrow[0]);
            float p1 = ex2(sacc[nf][1] - mrow[0]);
            float p2 = ex2(sacc[nf][2] - mrow[1]);
            float p3 = ex2(sacc[nf][3] - mrow[1]);
            sacc[nf][0] = p0; sacc[nf][1] = p1;
            sacc[nf][2] = p2; sacc[nf][3] = p3;
            psum[0] += p0 + p1;
            psum[1] += p2 + p3;
        }
#pragma unroll
        for (int off = 1; off <= 2; off <<= 1) {
            psum[0] += __shfl_xor_sync(0xffffffffu, psum[0], off);
            psum[1] += __shfl_xor_sync(0xffffffffu, psum[1], off);
        }
        lrow[0] = lrow[0] * alpha[0] + psum[0];
        lrow[1] = lrow[1] * alpha[1] + psum[1];
#pragma unroll
        for (int nf = 0; nf < 16; nf++) {
            oacc[nf][0] *= alpha[0]; oacc[nf][1] *= alpha[0];
            oacc[nf][2] *= alpha[1]; oacc[nf][3] *= alpha[1];
        }

        // ---- O += P V: P C-frag == A-frag, packed in registers ----
#pragma unroll
        for (int ks = 0; ks < 4; ks++) {
            uint32_t pfr[4];
            pfr[0] = pk2(sacc[2 * ks][0],     sacc[2 * ks][1]);
            pfr[1] = pk2(sacc[2 * ks][2],     sacc[2 * ks][3]);
            pfr[2] = pk2(sacc[2 * ks + 1][0], sacc[2 * ks + 1][1]);
            pfr[3] = pk2(sacc[2 * ks + 1][2], sacc[2 * ks + 1][3]);
            uint32_t vfr[2][2];
#pragma unroll
            for (int nf2 = 0; nf2 < 8; nf2++) {
                ldsm4(vfr[0][0], vfr[0][1], vfr[1][0], vfr[1][1],
                      vB[buf] + ((nf2 * 16 + lrowB) * VTP + ks * 16 + lkB) * 2);
                mma16816(oacc[2 * nf2],     pfr, vfr[0]);
                mma16816(oacc[2 * nf2 + 1], pfr, vfr[1]);
            }
        }

        __syncthreads();                      // all warps done with buf
        if (jt + 2 <= qblk) issueKV(jt + 2, buf);
        if (jt + 1 <= qblk) {
            if (jt + 2 <= qblk) { CP_WAIT(1); } else { CP_WAIT(0); }
            __syncthreads();                  // KV(jt+1) visible
        }
    }

    // ---- epilogue: normalize, write fp16 into g_oh [b,t,h*d] ----
    const int b = bh >> 3, h = bh & 7;
    const float invl0 = 1.0f / lrow[0];
    const float invl1 = 1.0f / lrow[1];
    const int t0 = qblk * 64 + wr * 16 + g;
    __half* dst0 = g_oh + (size_t)(b * T_ + t0) * M_ + h * D_;
    __half* dst1 = g_oh + (size_t)(b * T_ + t0 + 8) * M_ + h * D_;
#pragma unroll
    for (int nf = 0; nf < 16; nf++) {
        int col = 8 * nf + 2 * lq;
        *(uint32_t*)(dst0 + col) = pk2(oacc[nf][0] * invl0, oacc[nf][1] * invl0);
        *(uint32_t*)(dst1 + col) = pk2(oacc[nf][2] * invl1, oacc[nf][3] * invl1);
    }
}

// ---------------------------------------------------------------------------
extern "C" void kernel_launch(void* const* d_in, const int* in_sizes, int n_in,
                              void* d_out, int out_size)
{
    const float* x  = (const float*)d_in[0];
    const float* wq = (const float*)d_in[1];
    const float* wk = (const float*)d_in[2];
    const float* wv = (const float*)d_in[3];
    const float* wo = (const float*)d_in[4];
    float* out = (float*)d_out;

    cudaFuncSetAttribute(gemm_cp<0>,
                         cudaFuncAttributeMaxDynamicSharedMemorySize, GEMM_SMEM_BYTES);
    cudaFuncSetAttribute(gemm_cp<1>,
                         cudaFuncAttributeMaxDynamicSharedMemorySize, GEMM_SMEM_BYTES);
    cudaFuncSetAttribute(attn_mma,
                         cudaFuncAttributeMaxDynamicSharedMemorySize, ATTN_SMEM_BYTES);

    // fp16 pre-conversion (+W transpose) + rope table
    conv_x<<<4096, 256>>>(x);
    conv_w<<<dim3(32, 32, 4), dim3(32, 8)>>>(wq, wk, wv, wo);
    csn_kernel<<<256, 256>>>();

    // QKV projection (q,k -> fp16 [b,h,t,d]; v -> fp16 transposed)
    gemm_cp<0><<<dim3(8, 32, 3), 256, GEMM_SMEM_BYTES>>>(nullptr);

    // Fractional RoPE in-place (Q pre-scaled)
    rope_kernel<<<dim3(T_ / 4, BH_), 256>>>();

    // fp16 flash attention (P in registers)
    attn_mma<<<dim3(T_ / 64, BH_), 128, ATTN_SMEM_BYTES>>>();

    // Output projection
    gemm_cp<1><<<dim3(8, 32), 256, GEMM_SMEM_BYTES>>>(out);
}

// round 13
// speedup vs baseline: 2.0125x; 1.0191x over previous
#include <cuda_runtime.h>
#include <cuda_fp16.h>
#include <cstdint>
#include <math.h>

#define B_ 2
#define T_ 2048
#define M_ 1024
#define H_ 8
#define D_ 128
#define BH_ (B_*H_)

// Scratch (allocation-free: device globals)
__device__ __half g_qh[BH_ * T_ * D_];         // fp16 q [b,h,t,d] (rope in-place)
__device__ __half g_kh[BH_ * T_ * D_];         // fp16 k [b,h,t,d] (rope in-place)
__device__ __half g_vh[BH_ * T_ * D_];         // fp16 v TRANSPOSED [b,h,d,t]
__device__ __half g_oh[B_ * T_ * M_];          // fp16 attention out [b,t,h*d]
__device__ __half g_xh[B_ * T_ * M_];          // fp16(x)
__device__ __half g_wh[4 * M_ * M_];           // fp16 W TRANSPOSED [z][n][k]
__device__ float2 g_csn[T_ * 32];              // rope cos/sin table

__device__ __forceinline__ float ex2(float x) {
    float r;
    asm("ex2.approx.ftz.f32 %0, %1;" : "=f"(r) : "f"(x));
    return r;
}
__device__ __forceinline__ uint32_t pk2(float a, float b) {
    __half2 h = __floats2half2_rn(a, b);
    return *(uint32_t*)&h;
}
__device__ __forceinline__ void mma16816(float c[4], const uint32_t a[4],
                                         const uint32_t b[2]) {
    asm volatile(
        "mma.sync.aligned.m16n8k16.row.col.f32.f16.f16.f32 "
        "{%0,%1,%2,%3}, {%4,%5,%6,%7}, {%8,%9}, {%0,%1,%2,%3};"
        : "+f"(c[0]), "+f"(c[1]), "+f"(c[2]), "+f"(c[3])
        : "r"(a[0]), "r"(a[1]), "r"(a[2]), "r"(a[3]), "r"(b[0]), "r"(b[1]));
}
__device__ __forceinline__ void ldsm4(uint32_t& r0, uint32_t& r1,
                                      uint32_t& r2, uint32_t& r3, uint32_t addr) {
    asm volatile("ldmatrix.sync.aligned.m8n8.x4.shared.b16 {%0,%1,%2,%3}, [%4];"
                 : "=r"(r0), "=r"(r1), "=r"(r2), "=r"(r3) : "r"(addr));
}
__device__ __forceinline__ void cp16(uint32_t smem_dst, const void* gptr) {
    asm volatile("cp.async.cg.shared.global [%0], [%1], 16;"
                 :: "r"(smem_dst), "l"(gptr));
}
#define CP_COMMIT() asm volatile("cp.async.commit_group;" ::: "memory")
#define CP_WAIT(n)  asm volatile("cp.async.wait_group %0;" :: "n"(n) : "memory")

// ---------------------------------------------------------------------------
// fp16 pre-conversion + rope table
// ---------------------------------------------------------------------------
__global__ void conv_x(const float* __restrict__ x)
{
    int i = blockIdx.x * 256 + threadIdx.x;          // float4 index (1M total)
    float4 v = ((const float4*)x)[i];
    ((uint2*)g_xh)[i] = make_uint2(pk2(v.x, v.y), pk2(v.z, v.w));
}
// W transpose: g_wh[z][n][k] = fp16(W_z[k][n])
__global__ void conv_w(const float* __restrict__ wq, const float* __restrict__ wk,
                       const float* __restrict__ wv, const float* __restrict__ wo)
{
    __shared__ __half t[32][33];
    const int z = blockIdx.z;
    const float* src = (z == 0) ? wq : (z == 1) ? wk : (z == 2) ? wv : wo;
    __half* dst = g_wh + (size_t)z * M_ * M_;

    int x = blockIdx.x * 32 + threadIdx.x;    // n
    int y = blockIdx.y * 32 + threadIdx.y;    // k
#pragma unroll
    for (int i = 0; i < 32; i += 8)
        t[threadIdx.y + i][threadIdx.x] = __float2half_rn(src[(size_t)(y + i) * 1024 + x]);
    __syncthreads();
    int xn = blockIdx.x * 32, yk = blockIdx.y * 32;
#pragma unroll
    for (int i = 0; i < 32; i += 8)
        dst[(size_t)(xn + threadIdx.y + i) * 1024 + yk + threadIdx.x] =
            t[threadIdx.x][threadIdx.y + i];
}
__global__ void csn_kernel()
{
    int i = blockIdx.x * 256 + threadIdx.x;     // 65536 total
    int t = i >> 5, d = i & 31;
    float freq = powf(10000.0f, -(float)d * (1.0f / 32.0f));
    float sn, cs;
    sincosf((float)t * freq, &sn, &cs);
    g_csn[i] = make_float2(cs, sn);
}

// ---------------------------------------------------------------------------
// fp16 mma.sync GEMM, PERSISTENT: grid 296 (MODE 0) loops over 768 jobs
// (z,by,bx); MODE 1 grid 256, one job each. CTA tile 128x128, 8 warps,
// warp 64x32, K-chunk 64, 3-stage cp.async, ldmatrix.x4.
// ---------------------------------------------------------------------------
#define APH 72
#define BPH 72
#define A_BYTES (128 * APH * 2)
#define B_BYTES (128 * BPH * 2)
#define STG_BYTES (A_BYTES + B_BYTES)          // 36864
#define GEMM_SMEM_BYTES (3 * STG_BYTES)        // 110592

template <int MODE>
__global__ void __launch_bounds__(256, 2) gemm_cp(float* __restrict__ Cout)
{
    extern __shared__ __half smh[];

    const int tid  = threadIdx.x;
    const int lane = tid & 31;
    const int wid  = tid >> 5;
    const int wm   = wid & 1;
    const int wn   = wid >> 1;
    const int g    = lane >> 2;
    const int lq   = lane & 3;

    const uint32_t smbase = (uint32_t)__cvta_generic_to_shared(smh);

    const int lrowA = wm * 64 + (lane & 7) + ((lane >> 3) & 1) * 8;
    const int lkA   = (lane >> 4) * 8;
    const int lrowB = wn * 32 + (lane & 7) + ((lane >> 4) << 3);
    const int lkB   = ((lane >> 3) & 1) * 8;

    const int NJOBS = (MODE == 0) ? 768 : 256;

    for (int job = blockIdx.x; job < NJOBS; job += gridDim.x) {
        int z, by, bx;
        if (MODE == 0) {
            z = job >> 8;
            by = (job & 255) >> 3;
            bx = job & 7;
        } else {
            z = 3;
            by = job >> 3;
            bx = job & 7;
        }
        const __half* Ap = (MODE == 0) ? g_xh : g_oh;
        const __half* Wt = g_wh + (size_t)z * M_ * M_;
        const int r0 = by * 128;
        const int c0 = bx * 128;

        auto issue = [&](int c) {
            const uint32_t aB = smbase + (c % 3) * STG_BYTES;
            const uint32_t bB = aB + A_BYTES;
            const int kc = c * 64;
#pragma unroll
            for (int it = 0; it < 4; it++) {
                int idx = tid + it * 256;
                int r = idx >> 3, c8 = idx & 7;
                cp16(aB + (r * APH + 8 * c8) * 2,
                     Ap + (size_t)(r0 + r) * 1024 + kc + 8 * c8);
                cp16(bB + (r * BPH + 8 * c8) * 2,
                     Wt + (size_t)(c0 + r) * 1024 + kc + 8 * c8);
            }
            CP_COMMIT();
        };

        float acc[4][4][4];
#pragma unroll
        for (int i = 0; i < 4; i++)
#pragma unroll
            for (int j = 0; j < 4; j++)
#pragma unroll
                for (int e = 0; e < 4; e++) acc[i][j][e] = 0.0f;

        issue(0);
        issue(1);

        for (int c = 0; c < 16; c++) {
            if (c < 14) { CP_WAIT(1); } else { CP_WAIT(0); }
            __syncthreads();

            const uint32_t aB = smbase + (c % 3) * STG_BYTES;
            const uint32_t bB = aB + A_BYTES;

#pragma unroll
            for (int ks = 0; ks < 4; ks++) {
                uint32_t afr[4][4];
#pragma unroll
                for (int mf = 0; mf < 4; mf++)
                    ldsm4(afr[mf][0], afr[mf][1], afr[mf][2], afr[mf][3],
                          aB + ((lrowA + mf * 16) * APH + ks * 16 + lkA) * 2);
                uint32_t bfr[4][2];
#pragma unroll
                for (int nf2 = 0; nf2 < 2; nf2++)
                    ldsm4(bfr[2 * nf2][0], bfr[2 * nf2][1],
                          bfr[2 * nf2 + 1][0], bfr[2 * nf2 + 1][1],
                          bB + ((lrowB + nf2 * 16) * BPH + ks * 16 + lkB) * 2);
#pragma unroll
                for (int mf = 0; mf < 4; mf++)
#pragma unroll
                    for (int nf = 0; nf < 4; nf++)
                        mma16816(acc[mf][nf], afr[mf], bfr[nf]);
            }

            if (c + 2 < 16) issue(c + 2);
        }

        // ---- epilogue ----
#pragma unroll
        for (int mf = 0; mf < 4; mf++) {
#pragma unroll
            for (int half = 0; half < 2; half++) {
                int row = r0 + wm * 64 + mf * 16 + g + half * 8;
#pragma unroll
                for (int nf = 0; nf < 4; nf++) {
                    int col = c0 + wn * 32 + nf * 8 + 2 * lq;
                    float v0 = half ? acc[mf][nf][2] : acc[mf][nf][0];
                    float v1 = half ? acc[mf][nf][3] : acc[mf][nf][1];
                    if (MODE == 0) {
                        int bb = row >> 11, t = row & 2047;
                        int h = col >> 7, d = col & 127;
                        if (z == 2) {
                            __half* dv = g_vh + ((size_t)(bb * H_ + h) * D_ + d) * T_ + t;
                            dv[0]  = __float2half_rn(v0);
                            dv[T_] = __float2half_rn(v1);
                        } else {
                            __half* O = (z == 0) ? g_qh : g_kh;
                            *(uint32_t*)(O + ((size_t)(bb * H_ + h) * T_ + t) * D_ + d) =
                                pk2(v0, v1);
                        }
                    } else {
                        *(float2*)(Cout + (size_t)row * 1024 + col) = make_float2(v0, v1);
                    }
                }
            }
        }
        __syncthreads();   // all warps done with smem before next job reuses it
    }
}

// ---------------------------------------------------------------------------
// Fractional RoPE in-place on fp16 q/k; Q pre-scaled by log2(e)/128.
// ---------------------------------------------------------------------------
#define KC_ (1.44269504f / 128.0f)

__global__ void rope_kernel()
{
    const int t  = blockIdx.x * 4 + (threadIdx.x >> 6);
    const int bh = blockIdx.y;
    const int r  = threadIdx.x & 63;
    const int d  = r & 31;
    const bool isq = (r < 32);
    __half* p = (isq ? g_qh : g_kh) + ((size_t)bh * T_ + t) * D_;

    float2 cssn = g_csn[t * 32 + d];
    float e = __half2float(p[d]), o = __half2float(p[d + 32]);
    if (isq) {
        p[d]      = __float2half_rn((e * cssn.x - o * cssn.y) * KC_);
        p[d + 32] = __float2half_rn((e * cssn.y + o * cssn.x) * KC_);
        p[d + 64] = __float2half_rn(__half2float(p[d + 64]) * KC_);
        p[d + 96] = __float2half_rn(__half2float(p[d + 96]) * KC_);
    } else {
        p[d]      = __float2half_rn(e * cssn.x - o * cssn.y);
        p[d + 32] = __float2half_rn(e * cssn.y + o * cssn.x);
    }
}

// ---------------------------------------------------------------------------
// fp16 flash attention: Br=Bc=64, 4 warps, 3 CTAs/SM, K/V double-buffered,
// P in registers, exp2 softmax, reverse qblk order.
// ---------------------------------------------------------------------------
#define QKP 136
#define VTP 72
#define KA_OFF 0
#define KB_OFF 17408
#define VA_OFF 34816
#define VB_OFF 53248
#define ATTN_SMEM_BYTES 71680

__global__ void __launch_bounds__(128, 3) attn_mma()
{
    extern __shared__ __half smh[];
    const uint32_t smbase = (uint32_t)__cvta_generic_to_shared(smh);
    const uint32_t kB[2] = { smbase + KA_OFF, smbase + KB_OFF };
    const uint32_t vB[2] = { smbase + VA_OFF, smbase + VB_OFF };

    const int qblk = gridDim.x - 1 - blockIdx.x;   // longest first
    const int bh   = blockIdx.y;
    const __half* Qg = g_qh + ((size_t)bh * T_ + (size_t)qblk * 64) * D_;
    const __half* Kg = g_kh + (size_t)bh * T_ * D_;
    const __half* Vg = g_vh + (size_t)bh * D_ * T_;   // [d][t]

    const int tid  = threadIdx.x;
    const int lane = tid & 31;
    const int wr   = tid >> 5;
    const int g    = lane >> 2;
    const int lq   = lane & 3;

    const int lrowQ = (lane & 7) + ((lane >> 3) & 1) * 8;
    const int lkQ   = (lane >> 4) * 8;
    const int lrowB = (lane & 7) + ((lane >> 4) << 3);
    const int lkB   = ((lane >> 3) & 1) * 8;

    auto issueKV = [&](int jt, int buf) {
#pragma unroll
        for (int it = 0; it < 8; it++) {
            int idx = tid + it * 128;
            int r = idx >> 4, c8 = idx & 15;
            cp16(kB[buf] + (r * QKP + 8 * c8) * 2,
                 Kg + (size_t)(jt * 64 + r) * D_ + 8 * c8);
        }
#pragma unroll
        for (int it = 0; it < 8; it++) {
            int idx = tid + it * 128;
            int r = idx >> 3, c8 = idx & 7;
            cp16(vB[buf] + (r * VTP + 8 * c8) * 2,
                 Vg + (size_t)r * T_ + jt * 64 + 8 * c8);
        }
        CP_COMMIT();
    };

    // ---- stage Q into Ka, load register fragments ----
#pragma unroll
    for (int it = 0; it < 8; it++) {
        int idx = tid + it * 128;
        int r = idx >> 4, c8 = idx & 15;
        cp16(kB[0] + (r * QKP + 8 * c8) * 2, Qg + (size_t)r * D_ + 8 * c8);
    }
    CP_COMMIT();
    CP_WAIT(0);
    __syncthreads();

    uint32_t qfr[8][4];
#pragma unroll
    for (int ks = 0; ks < 8; ks++)
        ldsm4(qfr[ks][0], qfr[ks][1], qfr[ks][2], qfr[ks][3],
              kB[0] + ((wr * 16 + lrowQ) * QKP + ks * 16 + lkQ) * 2);
    __syncthreads();   // Q readers done before K(0) overwrites Ka

    issueKV(0, 0);
    if (qblk >= 1) issueKV(1, 1);
    if (qblk >= 1) { CP_WAIT(1); } else { CP_WAIT(0); }
    __syncthreads();

    float oacc[16][4];
#pragma unroll
    for (int nf = 0; nf < 16; nf++)
#pragma unroll
        for (int e = 0; e < 4; e++) oacc[nf][e] = 0.0f;
    float mrow[2] = { -1e30f, -1e30f };
    float lrow[2] = { 0.0f, 0.0f };

    for (int jt = 0; jt <= qblk; jt++) {
        const int buf = jt & 1;

        // ---- S = Q K^T (exp2-domain) ----
        float sacc[8][4];
#pragma unroll
        for (int nf = 0; nf < 8; nf++)
#pragma unroll
            for (int e = 0; e < 4; e++) sacc[nf][e] = 0.0f;

#pragma unroll
        for (int ks = 0; ks < 8; ks++) {
            uint32_t bfr[8][2];
#pragma unroll
            for (int nf2 = 0; nf2 < 4; nf2++)
                ldsm4(bfr[2 * nf2][0], bfr[2 * nf2][1],
                      bfr[2 * nf2 + 1][0], bfr[2 * nf2 + 1][1],
                      kB[buf] + ((nf2 * 16 + lrowB) * QKP + ks * 16 + lkB) * 2);
#pragma unroll
            for (int nf = 0; nf < 8; nf++)
                mma16816(sacc[nf], qfr[ks], bfr[nf]);
        }

        // ---- softmax ----
        if (jt == qblk) {
#pragma unroll
            for (int nf = 0; nf < 8; nf++)
#pragma unroll
                for (int e = 0; e < 4; e++) {
                    int col = nf * 8 + 2 * lq + (e & 1);
                    int row = wr * 16 + g + (e >> 1) * 8;
                    if (col > row) sacc[nf][e] = -1e30f;
                }
        }

        float zmax[2] = { -1e30f, -1e30f };
#pragma unroll
        for (int nf = 0; nf < 8; nf++) {
            zmax[0] = fmaxf(zmax[0], fmaxf(sacc[nf][0], sacc[nf][1]));
            zmax[1] = fmaxf(zmax[1], fmaxf(sacc[nf][2], sacc[nf][3]));
        }
#pragma unroll
        for (int off = 1; off <= 2; off <<= 1) {
            zmax[0] = fmaxf(zmax[0], __shfl_xor_sync(0xffffffffu, zmax[0], off));
            zmax[1] = fmaxf(zmax[1], __shfl_xor_sync(0xffffffffu, zmax[1], off));
        }

        float alpha[2], psum[2] = { 0.0f, 0.0f };
#pragma unroll
        for (int rr = 0; rr < 2; rr++) {
            float mn = fmaxf(mrow[rr], zmax[rr]);
            alpha[rr] = ex2(mrow[rr] - mn);
            mrow[rr] = mn;
        }
#pragma unroll
        for (int nf = 0; nf < 8; nf++) {
            float p0 = ex2(sacc[nf][0] - mrow[0]);
            float p1 = ex2(sacc[nf][1] - mrow[0]);
            float p2 = ex2(sacc[nf][2] - mrow[1]);
            float p3 = ex2(sacc[nf][3] - mrow[1]);
            sacc[nf][0] = p0; sacc[nf][1] = p1;
            sacc[nf][2] = p2; sacc[nf][3] = p3;
            psum[0] += p0 + p1;
            psum[1] += p2 + p3;
        }
#pragma unroll
        for (int off = 1; off <= 2; off <<= 1) {
            psum[0] += __shfl_xor_sync(0xffffffffu, psum[0], off);
            psum[1] += __shfl_xor_sync(0xffffffffu, psum[1], off);
        }
        lrow[0] = lrow[0] * alpha[0] + psum[0];
        lrow[1] = lrow[1] * alpha[1] + psum[1];
#pragma unroll
        for (int nf = 0; nf < 16; nf++) {
            oacc[nf][0] *= alpha[0]; oacc[nf][1] *= alpha[0];
            oacc[nf][2] *= alpha[1]; oacc[nf][3] *= alpha[1];
        }

        // ---- O += P V: P C-frag == A-frag, packed in registers ----
#pragma unroll
        for (int ks = 0; ks < 4; ks++) {
            uint32_t pfr[4];
            pfr[0] = pk2(sacc[2 * ks][0],     sacc[2 * ks][1]);
            pfr[1] = pk2(sacc[2 * ks][2],     sacc[2 * ks][3]);
            pfr[2] = pk2(sacc[2 * ks + 1][0], sacc[2 * ks + 1][1]);
            pfr[3] = pk2(sacc[2 * ks + 1][2], sacc[2 * ks + 1][3]);
            uint32_t vfr[2][2];
#pragma unroll
            for (int nf2 = 0; nf2 < 8; nf2++) {
                ldsm4(vfr[0][0], vfr[0][1], vfr[1][0], vfr[1][1],
                      vB[buf] + ((nf2 * 16 + lrowB) * VTP + ks * 16 + lkB) * 2);
                mma16816(oacc[2 * nf2],     pfr, vfr[0]);
                mma16816(oacc[2 * nf2 + 1], pfr, vfr[1]);
            }
        }

        __syncthreads();                      // all warps done with buf
        if (jt + 2 <= qblk) issueKV(jt + 2, buf);
        if (jt + 1 <= qblk) {
            if (jt + 2 <= qblk) { CP_WAIT(1); } else { CP_WAIT(0); }
            __syncthreads();                  // KV(jt+1) visible
        }
    }

    // ---- epilogue: normalize, write fp16 into g_oh [b,t,h*d] ----
    const int b = bh >> 3, h = bh & 7;
    const float invl0 = 1.0f / lrow[0];
    const float invl1 = 1.0f / lrow[1];
    const int t0 = qblk * 64 + wr * 16 + g;
    __half* dst0 = g_oh + (size_t)(b * T_ + t0) * M_ + h * D_;
    __half* dst1 = g_oh + (size_t)(b * T_ + t0 + 8) * M_ + h * D_;
#pragma unroll
    for (int nf = 0; nf < 16; nf++) {
        int col = 8 * nf + 2 * lq;
        *(uint32_t*)(dst0 + col) = pk2(oacc[nf][0] * invl0, oacc[nf][1] * invl0);
        *(uint32_t*)(dst1 + col) = pk2(oacc[nf][2] * invl1, oacc[nf][3] * invl1);
    }
}

// ---------------------------------------------------------------------------
extern "C" void kernel_launch(void* const* d_in, const int* in_sizes, int n_in,
                              void* d_out, int out_size)
{
    const float* x  = (const float*)d_in[0];
    const float* wq = (const float*)d_in[1];
    const float* wk = (const float*)d_in[2];
    const float* wv = (const float*)d_in[3];
    const float* wo = (const float*)d_in[4];
    float* out = (float*)d_out;

    cudaFuncSetAttribute(gemm_cp<0>,
                         cudaFuncAttributeMaxDynamicSharedMemorySize, GEMM_SMEM_BYTES);
    cudaFuncSetAttribute(gemm_cp<1>,
                         cudaFuncAttributeMaxDynamicSharedMemorySize, GEMM_SMEM_BYTES);
    cudaFuncSetAttribute(attn_mma,
                         cudaFuncAttributeMaxDynamicSharedMemorySize, ATTN_SMEM_BYTES);

    // fp16 pre-conversion (+W transpose) + rope table
    conv_x<<<4096, 256>>>(x);
    conv_w<<<dim3(32, 32, 4), dim3(32, 8)>>>(wq, wk, wv, wo);
    csn_kernel<<<256, 256>>>();

    // QKV projection: persistent grid (296 CTAs over 768 jobs)
    gemm_cp<0><<<296, 256, GEMM_SMEM_BYTES>>>(nullptr);

    // Fractional RoPE in-place (Q pre-scaled)
    rope_kernel<<<dim3(T_ / 4, BH_), 256>>>();

    // fp16 flash attention (3 CTAs/SM)
    attn_mma<<<dim3(T_ / 64, BH_), 128, ATTN_SMEM_BYTES>>>();

    // Output projection (256 jobs, direct grid)
    gemm_cp<1><<<256, 256, GEMM_SMEM_BYTES>>>(out);
}